// round 7
// baseline (speedup 1.0000x reference)
#include <cuda_runtime.h>
#include <cuda_fp16.h>
#include <cuda_bf16.h>

#define N_NODES 100000
#define N_EDGES 1600000
#define F 64
#define NCLS 16
#define NEG_SLOPE 0.01f

#define SCAN_BLK 1024
#define SCAN_NB ((N_NODES + SCAN_BLK - 1) / SCAN_BLK)   // 98

#define EB4   ((N_EDGES / 4 + 255) / 256)   // 1563 edge blocks
#define NB256 ((N_NODES + 255) / 256)       // 391 node blocks

typedef unsigned long long ull;

// ---------------- scratch (device globals; zero at module load) --------------
__device__ int    g_deg[N_NODES];        // histogram; restored to 0 each call
__device__ int    g_off[N_NODES + 1];
__device__ int    g_cursor[N_NODES];
__device__ int    g_csr[N_EDGES];
__device__ int    g_scan_incl[SCAN_NB];  // per-block aggregate
__device__ int    g_scan_flag[SCAN_NB];  // reset by hist_gemm each call
__device__ __half g_P[(size_t)N_NODES * F];   // fp16 messages
__device__ __half g_Pl[(size_t)N_NODES * F];  // fp16 pooled (exact)
__device__ float  g_H[(size_t)N_NODES * F];   // layer-1 output (fp32)

// ---------------- f32x2 helpers (sm_100+ packed fp32 FMA) --------------------
__device__ __forceinline__ void ffma2(ull& d, ull a, ull b) {
    asm("fma.rn.f32x2 %0, %1, %2, %0;" : "+l"(d) : "l"(a), "l"(b));
}
__device__ __forceinline__ ull pack2(float x) {
    ull r; asm("mov.b64 %0, {%1, %1};" : "=l"(r) : "f"(x)); return r;
}
__device__ __forceinline__ float2 unpack2(ull a) {
    float2 r; asm("mov.b64 {%0, %1}, %2;" : "=f"(r.x), "=f"(r.y) : "l"(a)); return r;
}

// ---------- GEMM body: acc[DOUT/2] (f32x2) += x(float4 rows) @ W(smem) -------
template <int DOUT>
__device__ __forceinline__ void gemm_row(const float4* __restrict__ xr,
                                         const ulonglong2* __restrict__ sW,
                                         ull* acc) {
    #pragma unroll
    for (int k4 = 0; k4 < F / 4; k4++) {
        float4 xv = xr[k4];
        float xs[4] = {xv.x, xv.y, xv.z, xv.w};
        #pragma unroll
        for (int kk = 0; kk < 4; kk++) {
            int k = k4 * 4 + kk;
            ull xk = pack2(xs[kk]);
            #pragma unroll
            for (int j4 = 0; j4 < DOUT / 4; j4++) {
                ulonglong2 w = sW[k * (DOUT / 4) + j4];
                ffma2(acc[2 * j4 + 0], xk, w.x);
                ffma2(acc[2 * j4 + 1], xk, w.y);
            }
        }
    }
}

// relu + fp16 store of 64 accumulated values
__device__ __forceinline__ void store_relu_fp16(ull* acc, __half* Yrow) {
    uint4* yr = (uint4*)Yrow;
    #pragma unroll
    for (int j8 = 0; j8 < F / 8; j8++) {
        unsigned u[4];
        #pragma unroll
        for (int q = 0; q < 4; q++) {
            float2 v = unpack2(acc[j8 * 4 + q]);
            __half2 h = __floats2half2_rn(fmaxf(v.x, 0.f), fmaxf(v.y, 0.f));
            u[q] = *reinterpret_cast<unsigned*>(&h);
        }
        uint4 o; o.x = u[0]; o.y = u[1]; o.z = u[2]; o.w = u[3];
        yr[j8] = o;
    }
}

// ------- K1: merged edge histogram + layer-1 pool GEMM + flag reset ----------
__global__ __launch_bounds__(256) void hist_gemm_kernel(
        const int4* __restrict__ dst4,
        const float* __restrict__ X, const float* __restrict__ W,
        const float* __restrict__ b, __half* __restrict__ Y) {
    __shared__ ulonglong2 sW[F * F / 4];
    __shared__ ull sb[F / 2];
    int t = threadIdx.x;

    if (blockIdx.x < EB4) {
        if (blockIdx.x == 0 && t < SCAN_NB) g_scan_flag[t] = 0;
        int i = blockIdx.x * 256 + t;
        if (i < N_EDGES / 4) {
            int4 d = __ldg(&dst4[i]);
            atomicAdd(&g_deg[d.x], 1);
            atomicAdd(&g_deg[d.y], 1);
            atomicAdd(&g_deg[d.z], 1);
            atomicAdd(&g_deg[d.w], 1);
        }
        return;
    }

    const ulonglong2* W2 = (const ulonglong2*)W;
    #pragma unroll
    for (int i = 0; i < F * F / 4; i += 256) sW[i + t] = W2[i + t];
    if (t < F / 2) sb[t] = ((const ull*)b)[t];
    __syncthreads();

    int r = (blockIdx.x - EB4) * 256 + t;
    if (r >= N_NODES) return;

    ull acc[F / 2];
    #pragma unroll
    for (int j = 0; j < F / 2; j++) acc[j] = sb[j];
    gemm_row<F>((const float4*)(X + (size_t)r * F), sW, acc);
    store_relu_fp16(acc, Y + (size_t)r * F);
}

// ------- single-kernel scan: decoupled lookback over 98 blocks ---------------
// All SCAN_NB blocks are co-resident (98 < 148 SMs), every block publishes its
// aggregate unconditionally before any wait, so the wait graph is acyclic.
__global__ __launch_bounds__(SCAN_BLK) void scan_kernel() {
    __shared__ int s[SCAN_BLK];
    __shared__ int s_carry;
    int t = threadIdx.x;
    int b = blockIdx.x;
    int idx = b * SCAN_BLK + t;
    int val = 0;
    if (idx < N_NODES) { val = g_deg[idx]; g_deg[idx] = 0; }
    s[t] = val;
    __syncthreads();
    #pragma unroll
    for (int o = 1; o < SCAN_BLK; o <<= 1) {
        int x = (t >= o) ? s[t - o] : 0;
        __syncthreads();
        s[t] += x;
        __syncthreads();
    }
    int incl = s[t];
    if (t == SCAN_BLK - 1) {
        g_scan_incl[b] = incl;          // block aggregate
        __threadfence();
        atomicExch(&g_scan_flag[b], 1); // publish (release)
    }
    // warp 0: sum all predecessor aggregates (no serial chain)
    if (t < 32) {
        int c = 0;
        for (int i = t; i < b; i += 32) {
            while (atomicAdd(&g_scan_flag[i], 0) == 0) { __nanosleep(40); }
            __threadfence();            // acquire before reading aggregate
            c += g_scan_incl[i];
        }
        #pragma unroll
        for (int o = 16; o; o >>= 1) c += __shfl_down_sync(0xffffffff, c, o);
        if (t == 0) s_carry = c;
    }
    __syncthreads();
    int off = s_carry + incl - val;     // exclusive global prefix
    if (idx < N_NODES) {
        g_off[idx] = off;
        g_cursor[idx] = off;
    }
    if (idx == 0) g_off[N_NODES] = N_EDGES;
}

__global__ void fill_csr_kernel(const int4* __restrict__ src4,
                                const int4* __restrict__ dst4) {
    int i = blockIdx.x * blockDim.x + threadIdx.x;
    if (i < N_EDGES / 4) {
        int4 s = __ldg(&src4[i]);
        int4 d = __ldg(&dst4[i]);
        g_csr[atomicAdd(&g_cursor[d.x], 1)] = s.x;
        g_csr[atomicAdd(&g_cursor[d.y], 1)] = s.y;
        g_csr[atomicAdd(&g_cursor[d.z], 1)] = s.z;
        g_csr[atomicAdd(&g_cursor[d.w], 1)] = s.w;
    }
}

// ---------------- segment max pool: warp per dst node, unroll 8 --------------
__global__ __launch_bounds__(256) void pool_kernel(const __half* __restrict__ P,
                                                   __half* __restrict__ Pl) {
    int gwarp = (blockIdx.x * 256 + threadIdx.x) >> 5;
    int lane  = threadIdx.x & 31;
    if (gwarp >= N_NODES) return;
    const __half2* P2 = (const __half2*)P;
    int s0 = g_off[gwarp];
    int s1 = g_off[gwarp + 1];
    __half2 m = __float2half2_rn(0.f);
    int e = s0;
    for (; e + 8 <= s1; e += 8) {
        int idx[8];
        #pragma unroll
        for (int q = 0; q < 8; q++) idx[q] = g_csr[e + q];
        __half2 a[8];
        #pragma unroll
        for (int q = 0; q < 8; q++) a[q] = __ldg(&P2[idx[q] * (F / 2) + lane]);
        __half2 m01 = __hmax2(a[0], a[1]), m23 = __hmax2(a[2], a[3]);
        __half2 m45 = __hmax2(a[4], a[5]), m67 = __hmax2(a[6], a[7]);
        m = __hmax2(m, __hmax2(__hmax2(m01, m23), __hmax2(m45, m67)));
    }
    for (; e + 4 <= s1; e += 4) {
        int i0 = g_csr[e + 0], i1 = g_csr[e + 1];
        int i2 = g_csr[e + 2], i3 = g_csr[e + 3];
        __half2 a0 = __ldg(&P2[i0 * (F / 2) + lane]);
        __half2 a1 = __ldg(&P2[i1 * (F / 2) + lane]);
        __half2 a2 = __ldg(&P2[i2 * (F / 2) + lane]);
        __half2 a3 = __ldg(&P2[i3 * (F / 2) + lane]);
        m = __hmax2(m, __hmax2(__hmax2(a0, a1), __hmax2(a2, a3)));
    }
    for (; e < s1; e++) {
        int i = g_csr[e];
        m = __hmax2(m, __ldg(&P2[i * (F / 2) + lane]));
    }
    ((__half2*)Pl)[gwarp * (F / 2) + lane] = m;
}

// ------- mid fused: H = leaky(X@Ws + PL@Wn + b1); P2 = relu(H@Wp2 + bp2) -----
// Dynamic smem layout: sWs | sWn | sWp | sb1 | sbp  (49,664 B)
#define MID_SMEM (3 * (F * F * 4) + 2 * (F * 4))

__global__ __launch_bounds__(256) void mid_kernel(
        const float* __restrict__ X, const __half* __restrict__ PL,
        const float* __restrict__ Ws, const float* __restrict__ Wn,
        const float* __restrict__ b1,
        const float* __restrict__ Wp2, const float* __restrict__ bp2,
        float* __restrict__ H, __half* __restrict__ P2out) {
    extern __shared__ char dsm[];
    ulonglong2* sWs = (ulonglong2*)dsm;
    ulonglong2* sWn = sWs + F * F / 4;
    ulonglong2* sWp = sWn + F * F / 4;
    ull* sb1 = (ull*)(sWp + F * F / 4);
    ull* sbp = sb1 + F / 2;

    int t = threadIdx.x;
    const ulonglong2* A = (const ulonglong2*)Ws;
    const ulonglong2* B = (const ulonglong2*)Wn;
    const ulonglong2* C = (const ulonglong2*)Wp2;
    #pragma unroll
    for (int i = 0; i < F * F / 4; i += 256) {
        sWs[i + t] = A[i + t]; sWn[i + t] = B[i + t]; sWp[i + t] = C[i + t];
    }
    if (t < F / 2) { sb1[t] = ((const ull*)b1)[t]; sbp[t] = ((const ull*)bp2)[t]; }
    __syncthreads();

    int r = blockIdx.x * 256 + t;
    if (r >= N_NODES) return;

    // ---- phase A: H row ----
    ull acc[F / 2];
    #pragma unroll
    for (int j = 0; j < F / 2; j++) acc[j] = sb1[j];

    gemm_row<F>((const float4*)(X + (size_t)r * F), sWs, acc);

    // neighbor term from fp16 pooled row
    const uint4* pr = (const uint4*)(PL + (size_t)r * F);
    #pragma unroll
    for (int j8 = 0; j8 < F / 8; j8++) {
        uint4 v = __ldg(&pr[j8]);
        unsigned hw[4] = {v.x, v.y, v.z, v.w};
        #pragma unroll
        for (int q = 0; q < 4; q++) {
            float2 f = __half22float2(*reinterpret_cast<__half2*>(&hw[q]));
            int k0 = j8 * 8 + 2 * q;
            ull xa = pack2(f.x);
            ull xb = pack2(f.y);
            #pragma unroll
            for (int j4 = 0; j4 < F / 4; j4++) {
                ulonglong2 wv = sWn[k0 * (F / 4) + j4];
                ffma2(acc[2 * j4 + 0], xa, wv.x);
                ffma2(acc[2 * j4 + 1], xa, wv.y);
            }
            #pragma unroll
            for (int j4 = 0; j4 < F / 4; j4++) {
                ulonglong2 wv = sWn[(k0 + 1) * (F / 4) + j4];
                ffma2(acc[2 * j4 + 0], xb, wv.x);
                ffma2(acc[2 * j4 + 1], xb, wv.y);
            }
        }
    }
    // leaky relu, store H (fp32)
    float4* hr = (float4*)(H + (size_t)r * F);
    #pragma unroll
    for (int j4 = 0; j4 < F / 4; j4++) {
        float2 v0 = unpack2(acc[2 * j4 + 0]);
        float2 v1 = unpack2(acc[2 * j4 + 1]);
        float a0 = (v0.x >= 0.f) ? v0.x : NEG_SLOPE * v0.x;
        float a1 = (v0.y >= 0.f) ? v0.y : NEG_SLOPE * v0.y;
        float a2 = (v1.x >= 0.f) ? v1.x : NEG_SLOPE * v1.x;
        float a3 = (v1.y >= 0.f) ? v1.y : NEG_SLOPE * v1.y;
        float4 o; o.x = a0; o.y = a1; o.z = a2; o.w = a3;
        hr[j4] = o;
    }

    // ---- phase B: P2 row = relu(H @ Wp2 + bp2), re-reading H (L1 hit) ----
    #pragma unroll
    for (int j = 0; j < F / 2; j++) acc[j] = sbp[j];
    gemm_row<F>((const float4*)(H + (size_t)r * F), sWp, acc);
    store_relu_fp16(acc, P2out + (size_t)r * F);
}

// ------- final GEMM: out[N,16] = H@Ws2 + PL@Wn2 + b2 -------------------------
__global__ __launch_bounds__(256) void gemm_out2_kernel(
        const float* __restrict__ X, const __half* __restrict__ PL,
        const float* __restrict__ Ws, const float* __restrict__ Wn,
        const float* __restrict__ b, float* __restrict__ Y) {
    const int DOUT = NCLS;
    __shared__ ulonglong2 sWs[F * DOUT / 4];
    __shared__ ulonglong2 sWn[F * DOUT / 4];
    __shared__ ull sb[DOUT / 2];
    int t = threadIdx.x;
    const ulonglong2* Ws2 = (const ulonglong2*)Ws;
    const ulonglong2* Wn2 = (const ulonglong2*)Wn;
    for (int i = t; i < F * DOUT / 4; i += 256) { sWs[i] = Ws2[i]; sWn[i] = Wn2[i]; }
    if (t < DOUT / 2) sb[t] = ((const ull*)b)[t];
    __syncthreads();

    int r = blockIdx.x * 256 + t;
    if (r >= N_NODES) return;

    ull acc[DOUT / 2];
    #pragma unroll
    for (int j = 0; j < DOUT / 2; j++) acc[j] = sb[j];

    gemm_row<DOUT>((const float4*)(X + (size_t)r * F), sWs, acc);

    const uint4* pr = (const uint4*)(PL + (size_t)r * F);
    #pragma unroll
    for (int j8 = 0; j8 < F / 8; j8++) {
        uint4 v = __ldg(&pr[j8]);
        unsigned hw[4] = {v.x, v.y, v.z, v.w};
        #pragma unroll
        for (int q = 0; q < 4; q++) {
            float2 f = __half22float2(*reinterpret_cast<__half2*>(&hw[q]));
            int k0 = j8 * 8 + 2 * q;
            ull xa = pack2(f.x);
            ull xb = pack2(f.y);
            #pragma unroll
            for (int j4 = 0; j4 < DOUT / 4; j4++) {
                ulonglong2 wv = sWn[k0 * (DOUT / 4) + j4];
                ffma2(acc[2 * j4 + 0], xa, wv.x);
                ffma2(acc[2 * j4 + 1], xa, wv.y);
            }
            #pragma unroll
            for (int j4 = 0; j4 < DOUT / 4; j4++) {
                ulonglong2 wv = sWn[(k0 + 1) * (DOUT / 4) + j4];
                ffma2(acc[2 * j4 + 0], xb, wv.x);
                ffma2(acc[2 * j4 + 1], xb, wv.y);
            }
        }
    }
    float4* yr = (float4*)(Y + (size_t)r * DOUT);
    #pragma unroll
    for (int j4 = 0; j4 < DOUT / 4; j4++) {
        float2 v0 = unpack2(acc[2 * j4 + 0]);
        float2 v1 = unpack2(acc[2 * j4 + 1]);
        float4 o; o.x = v0.x; o.y = v0.y; o.z = v1.x; o.w = v1.y;
        yr[j4] = o;
    }
}

// ---------------- launch -----------------------------------------------------
extern "C" void kernel_launch(void* const* d_in, const int* in_sizes, int n_in,
                              void* d_out, int out_size) {
    const float* in_feat = (const float*)d_in[0];
    const int*   src     = (const int*)d_in[1];
    const int*   dst     = (const int*)d_in[2];
    const float* W_pool1 = (const float*)d_in[3];
    const float* b_pool1 = (const float*)d_in[4];
    const float* W_self1 = (const float*)d_in[5];
    const float* W_neigh1= (const float*)d_in[6];
    const float* bias1   = (const float*)d_in[7];
    const float* W_pool2 = (const float*)d_in[8];
    const float* b_pool2 = (const float*)d_in[9];
    const float* W_self2 = (const float*)d_in[10];
    const float* W_neigh2= (const float*)d_in[11];
    const float* bias2   = (const float*)d_in[12];
    float* out = (float*)d_out;

    __half *dP, *dPl; float* dH;
    cudaGetSymbolAddress((void**)&dP, g_P);
    cudaGetSymbolAddress((void**)&dPl, g_Pl);
    cudaGetSymbolAddress((void**)&dH, g_H);

    cudaFuncSetAttribute(mid_kernel,
                         cudaFuncAttributeMaxDynamicSharedMemorySize, MID_SMEM);

    const int POOLB = (N_NODES * 32 + 255) / 256;

    // K1: flag reset + histogram + layer-1 pool GEMM
    hist_gemm_kernel<<<EB4 + NB256, 256>>>((const int4*)dst,
                                           in_feat, W_pool1, b_pool1, dP);
    // K2: single-pass scan (offsets + cursors)
    scan_kernel<<<SCAN_NB, SCAN_BLK>>>();
    // K3: CSR fill
    fill_csr_kernel<<<EB4, 256>>>((const int4*)src, (const int4*)dst);
    // K4: layer-1 pool
    pool_kernel<<<POOLB, 256>>>(dP, dPl);
    // K5: H + layer-2 pool GEMM (fused, dynamic smem)
    mid_kernel<<<NB256, 256, MID_SMEM>>>(in_feat, dPl, W_self1, W_neigh1, bias1,
                                         W_pool2, b_pool2, dH, dP);
    // K6: layer-2 pool
    pool_kernel<<<POOLB, 256>>>(dP, dPl);
    // K7: final output GEMM
    gemm_out2_kernel<<<NB256, 256>>>(dH, dPl, W_self2, W_neigh2, bias2, out);
}

// round 8
// speedup vs baseline: 1.0519x; 1.0519x over previous
#include <cuda_runtime.h>
#include <cuda_fp16.h>
#include <cuda_bf16.h>

#define N_NODES 100000
#define N_EDGES 1600000
#define F 64
#define NCLS 16
#define NEG_SLOPE 0.01f

#define SCAN_BLK 1024
#define SCAN_NB ((N_NODES + SCAN_BLK - 1) / SCAN_BLK)   // 98

#define EB4   ((N_EDGES / 4 + 255) / 256)   // 1563 edge blocks
#define NB256 ((N_NODES + 255) / 256)       // 391 node blocks

typedef unsigned long long ull;

// ---------------- scratch (device globals; zero at module load) --------------
__device__ int    g_deg[N_NODES];        // histogram; restored to 0 each call
__device__ int    g_off[N_NODES + 1];
__device__ int    g_cursor[N_NODES];
__device__ int    g_csr[N_EDGES];
__device__ int    g_scan_incl[SCAN_NB];  // per-block aggregate
__device__ int    g_scan_flag[SCAN_NB];  // reset by hist_gemm each call
__device__ __half g_P[(size_t)N_NODES * F];   // fp16 messages
__device__ __half g_Pl[(size_t)N_NODES * F];  // fp16 pooled (exact)
__device__ float  g_H[(size_t)N_NODES * F];   // layer-1 output (fp32)

// ---------------- f32x2 helpers (sm_100+ packed fp32 FMA) --------------------
__device__ __forceinline__ void ffma2(ull& d, ull a, ull b) {
    asm("fma.rn.f32x2 %0, %1, %2, %0;" : "+l"(d) : "l"(a), "l"(b));
}
__device__ __forceinline__ ull pack2(float x) {
    ull r; asm("mov.b64 %0, {%1, %1};" : "=l"(r) : "f"(x)); return r;
}
__device__ __forceinline__ float2 unpack2(ull a) {
    float2 r; asm("mov.b64 {%0, %1}, %2;" : "=f"(r.x), "=f"(r.y) : "l"(a)); return r;
}
__device__ __forceinline__ unsigned hmax2u(unsigned a, unsigned b) {
    __half2 r = __hmax2(*reinterpret_cast<__half2*>(&a),
                        *reinterpret_cast<__half2*>(&b));
    return *reinterpret_cast<unsigned*>(&r);
}

// ---------- GEMM body: acc[DOUT/2] (f32x2) += x(float4 rows) @ W(smem) -------
template <int DOUT>
__device__ __forceinline__ void gemm_row(const float4* __restrict__ xr,
                                         const ulonglong2* __restrict__ sW,
                                         ull* acc) {
    #pragma unroll
    for (int k4 = 0; k4 < F / 4; k4++) {
        float4 xv = __ldg(&xr[k4]);
        float xs[4] = {xv.x, xv.y, xv.z, xv.w};
        #pragma unroll
        for (int kk = 0; kk < 4; kk++) {
            int k = k4 * 4 + kk;
            ull xk = pack2(xs[kk]);
            #pragma unroll
            for (int j4 = 0; j4 < DOUT / 4; j4++) {
                ulonglong2 w = sW[k * (DOUT / 4) + j4];
                ffma2(acc[2 * j4 + 0], xk, w.x);
                ffma2(acc[2 * j4 + 1], xk, w.y);
            }
        }
    }
}

// relu + fp16 store of 64 accumulated values
__device__ __forceinline__ void store_relu_fp16(ull* acc, __half* Yrow) {
    uint4* yr = (uint4*)Yrow;
    #pragma unroll
    for (int j8 = 0; j8 < F / 8; j8++) {
        unsigned u[4];
        #pragma unroll
        for (int q = 0; q < 4; q++) {
            float2 v = unpack2(acc[j8 * 4 + q]);
            __half2 h = __floats2half2_rn(fmaxf(v.x, 0.f), fmaxf(v.y, 0.f));
            u[q] = *reinterpret_cast<unsigned*>(&h);
        }
        uint4 o; o.x = u[0]; o.y = u[1]; o.z = u[2]; o.w = u[3];
        yr[j8] = o;
    }
}

// ------- K1: merged edge histogram + layer-1 pool GEMM + flag reset ----------
__global__ __launch_bounds__(256) void hist_gemm_kernel(
        const int4* __restrict__ dst4,
        const float* __restrict__ X, const float* __restrict__ W,
        const float* __restrict__ b, __half* __restrict__ Y) {
    __shared__ ulonglong2 sW[F * F / 4];
    __shared__ ull sb[F / 2];
    int t = threadIdx.x;

    if (blockIdx.x < EB4) {
        if (blockIdx.x == 0 && t < SCAN_NB) g_scan_flag[t] = 0;
        int i = blockIdx.x * 256 + t;
        if (i < N_EDGES / 4) {
            int4 d = __ldg(&dst4[i]);
            atomicAdd(&g_deg[d.x], 1);
            atomicAdd(&g_deg[d.y], 1);
            atomicAdd(&g_deg[d.z], 1);
            atomicAdd(&g_deg[d.w], 1);
        }
        return;
    }

    const ulonglong2* W2 = (const ulonglong2*)W;
    #pragma unroll
    for (int i = 0; i < F * F / 4; i += 256) sW[i + t] = W2[i + t];
    if (t < F / 2) sb[t] = ((const ull*)b)[t];
    __syncthreads();

    int r = (blockIdx.x - EB4) * 256 + t;
    if (r >= N_NODES) return;

    ull acc[F / 2];
    #pragma unroll
    for (int j = 0; j < F / 2; j++) acc[j] = sb[j];
    gemm_row<F>((const float4*)(X + (size_t)r * F), sW, acc);
    store_relu_fp16(acc, Y + (size_t)r * F);
}

// ------- single-kernel scan: decoupled lookback over 98 blocks ---------------
// All SCAN_NB blocks are co-resident (98 < 148 SMs); every block publishes its
// aggregate unconditionally before waiting, so the wait graph is acyclic.
__global__ __launch_bounds__(SCAN_BLK) void scan_kernel() {
    __shared__ int s[SCAN_BLK];
    __shared__ int s_carry;
    int t = threadIdx.x;
    int b = blockIdx.x;
    int idx = b * SCAN_BLK + t;
    int val = 0;
    if (idx < N_NODES) { val = g_deg[idx]; g_deg[idx] = 0; }
    s[t] = val;
    __syncthreads();
    #pragma unroll
    for (int o = 1; o < SCAN_BLK; o <<= 1) {
        int x = (t >= o) ? s[t - o] : 0;
        __syncthreads();
        s[t] += x;
        __syncthreads();
    }
    int incl = s[t];
    if (t == SCAN_BLK - 1) {
        g_scan_incl[b] = incl;
        __threadfence();
        atomicExch(&g_scan_flag[b], 1);
    }
    if (t < 32) {
        int c = 0;
        for (int i = t; i < b; i += 32) {
            while (atomicAdd(&g_scan_flag[i], 0) == 0) { __nanosleep(40); }
            __threadfence();
            c += g_scan_incl[i];
        }
        #pragma unroll
        for (int o = 16; o; o >>= 1) c += __shfl_down_sync(0xffffffff, c, o);
        if (t == 0) s_carry = c;
    }
    __syncthreads();
    int off = s_carry + incl - val;
    if (idx < N_NODES) {
        g_off[idx] = off;
        g_cursor[idx] = off;
    }
    if (idx == 0) g_off[N_NODES] = N_EDGES;
}

__global__ void fill_csr_kernel(const int4* __restrict__ src4,
                                const int4* __restrict__ dst4) {
    int i = blockIdx.x * blockDim.x + threadIdx.x;
    if (i < N_EDGES / 4) {
        int4 s = __ldg(&src4[i]);
        int4 d = __ldg(&dst4[i]);
        g_csr[atomicAdd(&g_cursor[d.x], 1)] = s.x;
        g_csr[atomicAdd(&g_cursor[d.y], 1)] = s.y;
        g_csr[atomicAdd(&g_cursor[d.z], 1)] = s.z;
        g_csr[atomicAdd(&g_cursor[d.w], 1)] = s.w;
    }
}

// ---------------- segment max pool: warp per node, 4 edges per warp-instr ----
// Lane layout: grp = lane>>3 picks edge within batch of 4; sub = lane&7 picks
// a 16-byte chunk (4 half2) within the 128B feature row. One LDG.128 per lane
// loads 4 full edge rows per warp instruction. Tail edges handled by clamping
// the edge index (max is idempotent, duplicates are free). Cross-group combine
// via 2 shfl_xor rounds at the end.
__global__ __launch_bounds__(256) void pool_kernel(const __half* __restrict__ P,
                                                   __half* __restrict__ Pl) {
    int gwarp = (blockIdx.x * 256 + threadIdx.x) >> 5;
    int lane  = threadIdx.x & 31;
    if (gwarp >= N_NODES) return;
    int grp = lane >> 3;
    int sub = lane & 7;
    int s0 = g_off[gwarp];
    int s1 = g_off[gwarp + 1];
    unsigned m0 = 0, m1 = 0, m2 = 0, m3 = 0;   // 4x half2 zeros
    const uint4* Prow = (const uint4*)P;

    if (s0 < s1) {
        int last = s1 - 1;
        for (int e = s0; e < s1; e += 8) {
            int ea = min(e + grp, last);
            int eb = min(e + 4 + grp, last);
            int ia = g_csr[ea];
            int ib = g_csr[eb];
            uint4 va = __ldg(&Prow[ia * 8 + sub]);
            uint4 vb = __ldg(&Prow[ib * 8 + sub]);
            m0 = hmax2u(m0, hmax2u(va.x, vb.x));
            m1 = hmax2u(m1, hmax2u(va.y, vb.y));
            m2 = hmax2u(m2, hmax2u(va.z, vb.z));
            m3 = hmax2u(m3, hmax2u(va.w, vb.w));
        }
    }
    // combine the 4 edge-groups (lanes differing in bits 3,4 of lane id)
    m0 = hmax2u(m0, __shfl_xor_sync(0xffffffff, m0, 8));
    m1 = hmax2u(m1, __shfl_xor_sync(0xffffffff, m1, 8));
    m2 = hmax2u(m2, __shfl_xor_sync(0xffffffff, m2, 8));
    m3 = hmax2u(m3, __shfl_xor_sync(0xffffffff, m3, 8));
    m0 = hmax2u(m0, __shfl_xor_sync(0xffffffff, m0, 16));
    m1 = hmax2u(m1, __shfl_xor_sync(0xffffffff, m1, 16));
    m2 = hmax2u(m2, __shfl_xor_sync(0xffffffff, m2, 16));
    m3 = hmax2u(m3, __shfl_xor_sync(0xffffffff, m3, 16));
    if (lane < 8) {
        uint4 o; o.x = m0; o.y = m1; o.z = m2; o.w = m3;
        ((uint4*)(Pl + (size_t)gwarp * F))[sub] = o;
    }
}

// ---------------- plain pool GEMM (layer 2): P = relu(H @ Wp + b) ------------
__global__ __launch_bounds__(256) void gemm_pool_kernel(
        const float* __restrict__ X, const float* __restrict__ W,
        const float* __restrict__ b, __half* __restrict__ Y) {
    __shared__ ulonglong2 sW[F * F / 4];
    __shared__ ull sb[F / 2];
    int t = threadIdx.x;
    const ulonglong2* W2 = (const ulonglong2*)W;
    #pragma unroll
    for (int i = 0; i < F * F / 4; i += 256) sW[i + t] = W2[i + t];
    if (t < F / 2) sb[t] = ((const ull*)b)[t];
    __syncthreads();

    int r = blockIdx.x * 256 + t;
    if (r >= N_NODES) return;

    ull acc[F / 2];
    #pragma unroll
    for (int j = 0; j < F / 2; j++) acc[j] = sb[j];
    gemm_row<F>((const float4*)(X + (size_t)r * F), sW, acc);
    store_relu_fp16(acc, Y + (size_t)r * F);
}

// ------- GEMM: Y[N,DOUT] = act(X@Ws + PL(fp16)@Wn + b) -----------------------
template <int DOUT, int ACT>
__global__ __launch_bounds__(256) void gemm_out_kernel(
        const float* __restrict__ X, const __half* __restrict__ PL,
        const float* __restrict__ Ws, const float* __restrict__ Wn,
        const float* __restrict__ b, float* __restrict__ Y) {
    __shared__ ulonglong2 sWs[F * DOUT / 4];
    __shared__ ulonglong2 sWn[F * DOUT / 4];
    __shared__ ull sb[DOUT / 2];
    int t = threadIdx.x;
    const ulonglong2* Ws2 = (const ulonglong2*)Ws;
    const ulonglong2* Wn2 = (const ulonglong2*)Wn;
    for (int i = t; i < F * DOUT / 4; i += 256) { sWs[i] = Ws2[i]; sWn[i] = Wn2[i]; }
    if (t < DOUT / 2) sb[t] = ((const ull*)b)[t];
    __syncthreads();

    int r = blockIdx.x * 256 + t;
    if (r >= N_NODES) return;

    ull acc[DOUT / 2];
    #pragma unroll
    for (int j = 0; j < DOUT / 2; j++) acc[j] = sb[j];

    gemm_row<DOUT>((const float4*)(X + (size_t)r * F), sWs, acc);

    // neighbor term: PL row as fp16x2, 8 x LDG.128
    const uint4* pr = (const uint4*)(PL + (size_t)r * F);
    #pragma unroll
    for (int j8 = 0; j8 < F / 8; j8++) {
        uint4 v = __ldg(&pr[j8]);
        unsigned hw[4] = {v.x, v.y, v.z, v.w};
        #pragma unroll
        for (int q = 0; q < 4; q++) {
            float2 f = __half22float2(*reinterpret_cast<__half2*>(&hw[q]));
            int k0 = j8 * 8 + 2 * q;
            ull xa = pack2(f.x);
            ull xb = pack2(f.y);
            #pragma unroll
            for (int j4 = 0; j4 < DOUT / 4; j4++) {
                ulonglong2 wv = sWn[k0 * (DOUT / 4) + j4];
                ffma2(acc[2 * j4 + 0], xa, wv.x);
                ffma2(acc[2 * j4 + 1], xa, wv.y);
            }
            #pragma unroll
            for (int j4 = 0; j4 < DOUT / 4; j4++) {
                ulonglong2 wv = sWn[(k0 + 1) * (DOUT / 4) + j4];
                ffma2(acc[2 * j4 + 0], xb, wv.x);
                ffma2(acc[2 * j4 + 1], xb, wv.y);
            }
        }
    }
    float4* yr = (float4*)(Y + (size_t)r * DOUT);
    #pragma unroll
    for (int j4 = 0; j4 < DOUT / 4; j4++) {
        float2 v0 = unpack2(acc[2 * j4 + 0]);
        float2 v1 = unpack2(acc[2 * j4 + 1]);
        float a0 = v0.x, a1 = v0.y, a2 = v1.x, a3 = v1.y;
        if (ACT == 1) {
            a0 = (a0 >= 0.f) ? a0 : NEG_SLOPE * a0;
            a1 = (a1 >= 0.f) ? a1 : NEG_SLOPE * a1;
            a2 = (a2 >= 0.f) ? a2 : NEG_SLOPE * a2;
            a3 = (a3 >= 0.f) ? a3 : NEG_SLOPE * a3;
        }
        float4 o; o.x = a0; o.y = a1; o.z = a2; o.w = a3;
        yr[j4] = o;
    }
}

// ---------------- launch -----------------------------------------------------
extern "C" void kernel_launch(void* const* d_in, const int* in_sizes, int n_in,
                              void* d_out, int out_size) {
    const float* in_feat = (const float*)d_in[0];
    const int*   src     = (const int*)d_in[1];
    const int*   dst     = (const int*)d_in[2];
    const float* W_pool1 = (const float*)d_in[3];
    const float* b_pool1 = (const float*)d_in[4];
    const float* W_self1 = (const float*)d_in[5];
    const float* W_neigh1= (const float*)d_in[6];
    const float* bias1   = (const float*)d_in[7];
    const float* W_pool2 = (const float*)d_in[8];
    const float* b_pool2 = (const float*)d_in[9];
    const float* W_self2 = (const float*)d_in[10];
    const float* W_neigh2= (const float*)d_in[11];
    const float* bias2   = (const float*)d_in[12];
    float* out = (float*)d_out;

    __half *dP, *dPl; float* dH;
    cudaGetSymbolAddress((void**)&dP, g_P);
    cudaGetSymbolAddress((void**)&dPl, g_Pl);
    cudaGetSymbolAddress((void**)&dH, g_H);

    const int POOLB = (N_NODES * 32 + 255) / 256;

    // K1: flag reset + histogram + layer-1 pool GEMM
    hist_gemm_kernel<<<EB4 + NB256, 256>>>((const int4*)dst,
                                           in_feat, W_pool1, b_pool1, dP);
    // K2: single-pass scan (offsets + cursors)
    scan_kernel<<<SCAN_NB, SCAN_BLK>>>();
    // K3: CSR fill
    fill_csr_kernel<<<EB4, 256>>>((const int4*)src, (const int4*)dst);
    // K4: layer-1 pool
    pool_kernel<<<POOLB, 256>>>(dP, dPl);
    // K5: H = leaky(X@Ws1 + Pl@Wn1 + b1)
    gemm_out_kernel<64, 1><<<NB256, 256>>>(in_feat, dPl, W_self1, W_neigh1, bias1, dH);
    // K6: P = relu(H@Wp2 + bp2)
    gemm_pool_kernel<<<NB256, 256>>>(dH, W_pool2, b_pool2, dP);
    // K7: layer-2 pool
    pool_kernel<<<POOLB, 256>>>(dP, dPl);
    // K8: out = H@Ws2 + Pl@Wn2 + b2
    gemm_out_kernel<16, 0><<<NB256, 256>>>(dH, dPl, W_self2, W_neigh2, bias2, out);
}

// round 9
// speedup vs baseline: 1.1632x; 1.1059x over previous
#include <cuda_runtime.h>
#include <cuda_fp16.h>
#include <cuda_bf16.h>

#define N_NODES 100000
#define N_EDGES 1600000
#define F 64
#define NCLS 16
#define NEG_SLOPE 0.01f

#define SCAN_BLK 1024
#define SCAN_NB ((N_NODES + SCAN_BLK - 1) / SCAN_BLK)   // 98

#define EB4   ((N_EDGES / 4 + 255) / 256)   // 1563 edge blocks
#define NB256 ((N_NODES + 255) / 256)       // 391 node blocks
#define WSTRIDE 72                          // smem W row stride (bank-conflict-free)

typedef unsigned long long ull;

// ---------------- scratch (device globals; zero at module load) --------------
__device__ int    g_deg[N_NODES];
__device__ int    g_off[N_NODES + 1];
__device__ int    g_cursor[N_NODES];
__device__ int    g_csr[N_EDGES];
__device__ int    g_scan_incl[SCAN_NB];
__device__ int    g_scan_flag[SCAN_NB];
__device__ __half g_P[(size_t)N_NODES * F];
__device__ __half g_Pl[(size_t)N_NODES * F];
__device__ float  g_H[(size_t)N_NODES * F];

// ---------------- f32x2 helpers ----------------------------------------------
__device__ __forceinline__ void ffma2(ull& d, ull a, ull b) {
    asm("fma.rn.f32x2 %0, %1, %2, %0;" : "+l"(d) : "l"(a), "l"(b));
}
__device__ __forceinline__ ull pack2(float x) {
    ull r; asm("mov.b64 %0, {%1, %1};" : "=l"(r) : "f"(x)); return r;
}
__device__ __forceinline__ float2 unpack2(ull a) {
    float2 r; asm("mov.b64 {%0, %1}, %2;" : "=f"(r.x), "=f"(r.y) : "l"(a)); return r;
}
__device__ __forceinline__ unsigned hmax2u(unsigned a, unsigned b) {
    __half2 r = __hmax2(*reinterpret_cast<__half2*>(&a),
                        *reinterpret_cast<__half2*>(&b));
    return *reinterpret_cast<unsigned*>(&r);
}

// ---------------- tf32 helpers -----------------------------------------------
__device__ __forceinline__ unsigned f2tf32(float f) {
    unsigned u; asm("cvt.rna.tf32.f32 %0, %1;" : "=r"(u) : "f"(f)); return u;
}
__device__ __forceinline__ void mma_tf32(float* d, const unsigned* a,
                                         unsigned b0, unsigned b1) {
    asm volatile(
        "mma.sync.aligned.m16n8k8.row.col.f32.tf32.tf32.f32 "
        "{%0,%1,%2,%3}, {%4,%5,%6,%7}, {%8,%9}, {%0,%1,%2,%3};"
        : "+f"(d[0]), "+f"(d[1]), "+f"(d[2]), "+f"(d[3])
        : "r"(a[0]), "r"(a[1]), "r"(a[2]), "r"(a[3]), "r"(b0), "r"(b1));
}

// ---- tensor-core pool GEMM body: P[256 rows] = relu(X @ W + b) -> fp16 ------
// Block = 256 threads = 8 warps; warp handles 32 rows (2 m16 tiles).
// sWt: W as tf32 bits, [64][WSTRIDE]; sbias: 64 floats.
__device__ __forceinline__ void gemm_pool_tf32_body(
        const float* __restrict__ X, const unsigned* __restrict__ sWt,
        const float* __restrict__ sbias, __half* __restrict__ Y, int rowbase) {
    int lane = threadIdx.x & 31;
    int warp = threadIdx.x >> 5;
    int g = lane >> 2;          // 0..7
    int t4 = lane & 3;          // 0..3
    int wbase = rowbase + warp * 32;
    const int NMAX = N_NODES - 1;

    // clamped row indices for the 2 tiles (loads only; stores are predicated)
    int r0a = min(wbase + g,      NMAX), r0b = min(wbase + g + 8,  NMAX);
    int r1a = min(wbase + 16 + g, NMAX), r1b = min(wbase + 24 + g, NMAX);

    float acc[2][8][4];
    #pragma unroll
    for (int T = 0; T < 2; T++)
        #pragma unroll
        for (int nf = 0; nf < 8; nf++) {
            float bb0 = sbias[8 * nf + 2 * t4];
            float bb1 = sbias[8 * nf + 2 * t4 + 1];
            acc[T][nf][0] = bb0; acc[T][nf][1] = bb1;
            acc[T][nf][2] = bb0; acc[T][nf][3] = bb1;
        }

    #pragma unroll
    for (int kf = 0; kf < 8; kf++) {
        int k0 = 8 * kf + t4;
        unsigned a[2][4];
        a[0][0] = f2tf32(__ldg(&X[(size_t)r0a * F + k0]));
        a[0][1] = f2tf32(__ldg(&X[(size_t)r0b * F + k0]));
        a[0][2] = f2tf32(__ldg(&X[(size_t)r0a * F + k0 + 4]));
        a[0][3] = f2tf32(__ldg(&X[(size_t)r0b * F + k0 + 4]));
        a[1][0] = f2tf32(__ldg(&X[(size_t)r1a * F + k0]));
        a[1][1] = f2tf32(__ldg(&X[(size_t)r1b * F + k0]));
        a[1][2] = f2tf32(__ldg(&X[(size_t)r1a * F + k0 + 4]));
        a[1][3] = f2tf32(__ldg(&X[(size_t)r1b * F + k0 + 4]));
        #pragma unroll
        for (int nf = 0; nf < 8; nf++) {
            unsigned b0 = sWt[(8 * kf + t4) * WSTRIDE + 8 * nf + g];
            unsigned b1 = sWt[(8 * kf + t4 + 4) * WSTRIDE + 8 * nf + g];
            mma_tf32(acc[0][nf], a[0], b0, b1);
            mma_tf32(acc[1][nf], a[1], b0, b1);
        }
    }

    // epilogue: relu -> fp16, guarded stores
    #pragma unroll
    for (int T = 0; T < 2; T++) {
        int ra = wbase + 16 * T + g;
        int rb = ra + 8;
        #pragma unroll
        for (int nf = 0; nf < 8; nf++) {
            int col = 8 * nf + 2 * t4;
            if (ra < N_NODES) {
                __half2 h = __floats2half2_rn(fmaxf(acc[T][nf][0], 0.f),
                                              fmaxf(acc[T][nf][1], 0.f));
                *(__half2*)(Y + (size_t)ra * F + col) = h;
            }
            if (rb < N_NODES) {
                __half2 h = __floats2half2_rn(fmaxf(acc[T][nf][2], 0.f),
                                              fmaxf(acc[T][nf][3], 0.f));
                *(__half2*)(Y + (size_t)rb * F + col) = h;
            }
        }
    }
}

// stage W (fp32 [64][64]) as tf32 bits into sWt, bias into sbias
__device__ __forceinline__ void stage_w_tf32(
        const float* __restrict__ W, const float* __restrict__ b,
        unsigned* sWt, float* sbias) {
    int t = threadIdx.x;
    for (int i = t; i < F * F; i += 256) {
        int k = i >> 6, n = i & 63;
        sWt[k * WSTRIDE + n] = f2tf32(__ldg(&W[i]));
    }
    if (t < F) sbias[t] = b[t];
}

// ------- K1: merged edge histogram + layer-1 pool GEMM (tf32) + flag reset ---
__global__ __launch_bounds__(256) void hist_gemm_kernel(
        const int4* __restrict__ dst4,
        const float* __restrict__ X, const float* __restrict__ W,
        const float* __restrict__ b, __half* __restrict__ Y) {
    __shared__ unsigned sWt[F * WSTRIDE];
    __shared__ float sbias[F];
    int t = threadIdx.x;

    if (blockIdx.x < EB4) {
        if (blockIdx.x == 0 && t < SCAN_NB) g_scan_flag[t] = 0;
        int i = blockIdx.x * 256 + t;
        if (i < N_EDGES / 4) {
            int4 d = __ldg(&dst4[i]);
            atomicAdd(&g_deg[d.x], 1);
            atomicAdd(&g_deg[d.y], 1);
            atomicAdd(&g_deg[d.z], 1);
            atomicAdd(&g_deg[d.w], 1);
        }
        return;
    }

    stage_w_tf32(W, b, sWt, sbias);
    __syncthreads();
    gemm_pool_tf32_body(X, sWt, sbias, Y, (blockIdx.x - EB4) * 256);
}

// ---------------- layer-2 pool GEMM (tf32): P = relu(H @ Wp + b) -------------
__global__ __launch_bounds__(256) void gemm_pool_kernel(
        const float* __restrict__ X, const float* __restrict__ W,
        const float* __restrict__ b, __half* __restrict__ Y) {
    __shared__ unsigned sWt[F * WSTRIDE];
    __shared__ float sbias[F];
    stage_w_tf32(W, b, sWt, sbias);
    __syncthreads();
    gemm_pool_tf32_body(X, sWt, sbias, Y, blockIdx.x * 256);
}

// ------- single-kernel scan: decoupled lookback over 98 blocks ---------------
__global__ __launch_bounds__(SCAN_BLK) void scan_kernel() {
    __shared__ int s[SCAN_BLK];
    __shared__ int s_carry;
    int t = threadIdx.x;
    int b = blockIdx.x;
    int idx = b * SCAN_BLK + t;
    int val = 0;
    if (idx < N_NODES) { val = g_deg[idx]; g_deg[idx] = 0; }
    s[t] = val;
    __syncthreads();
    #pragma unroll
    for (int o = 1; o < SCAN_BLK; o <<= 1) {
        int x = (t >= o) ? s[t - o] : 0;
        __syncthreads();
        s[t] += x;
        __syncthreads();
    }
    int incl = s[t];
    if (t == SCAN_BLK - 1) {
        g_scan_incl[b] = incl;
        __threadfence();
        atomicExch(&g_scan_flag[b], 1);
    }
    if (t < 32) {
        int c = 0;
        for (int i = t; i < b; i += 32) {
            while (atomicAdd(&g_scan_flag[i], 0) == 0) { __nanosleep(40); }
            __threadfence();
            c += g_scan_incl[i];
        }
        #pragma unroll
        for (int o = 16; o; o >>= 1) c += __shfl_down_sync(0xffffffff, c, o);
        if (t == 0) s_carry = c;
    }
    __syncthreads();
    int off = s_carry + incl - val;
    if (idx < N_NODES) {
        g_off[idx] = off;
        g_cursor[idx] = off;
    }
    if (idx == 0) g_off[N_NODES] = N_EDGES;
}

__global__ void fill_csr_kernel(const int4* __restrict__ src4,
                                const int4* __restrict__ dst4) {
    int i = blockIdx.x * blockDim.x + threadIdx.x;
    if (i < N_EDGES / 4) {
        int4 s = __ldg(&src4[i]);
        int4 d = __ldg(&dst4[i]);
        g_csr[atomicAdd(&g_cursor[d.x], 1)] = s.x;
        g_csr[atomicAdd(&g_cursor[d.y], 1)] = s.y;
        g_csr[atomicAdd(&g_cursor[d.z], 1)] = s.z;
        g_csr[atomicAdd(&g_cursor[d.w], 1)] = s.w;
    }
}

// ---------------- segment max pool: warp per node, 4 edges per warp-instr ----
__global__ __launch_bounds__(256) void pool_kernel(const __half* __restrict__ P,
                                                   __half* __restrict__ Pl) {
    int gwarp = (blockIdx.x * 256 + threadIdx.x) >> 5;
    int lane  = threadIdx.x & 31;
    if (gwarp >= N_NODES) return;
    int grp = lane >> 3;
    int sub = lane & 7;
    int s0 = g_off[gwarp];
    int s1 = g_off[gwarp + 1];
    unsigned m0 = 0, m1 = 0, m2 = 0, m3 = 0;
    const uint4* Prow = (const uint4*)P;

    if (s0 < s1) {
        int last = s1 - 1;
        for (int e = s0; e < s1; e += 8) {
            int ea = min(e + grp, last);
            int eb = min(e + 4 + grp, last);
            int ia = g_csr[ea];
            int ib = g_csr[eb];
            uint4 va = __ldg(&Prow[ia * 8 + sub]);
            uint4 vb = __ldg(&Prow[ib * 8 + sub]);
            m0 = hmax2u(m0, hmax2u(va.x, vb.x));
            m1 = hmax2u(m1, hmax2u(va.y, vb.y));
            m2 = hmax2u(m2, hmax2u(va.z, vb.z));
            m3 = hmax2u(m3, hmax2u(va.w, vb.w));
        }
    }
    m0 = hmax2u(m0, __shfl_xor_sync(0xffffffff, m0, 8));
    m1 = hmax2u(m1, __shfl_xor_sync(0xffffffff, m1, 8));
    m2 = hmax2u(m2, __shfl_xor_sync(0xffffffff, m2, 8));
    m3 = hmax2u(m3, __shfl_xor_sync(0xffffffff, m3, 8));
    m0 = hmax2u(m0, __shfl_xor_sync(0xffffffff, m0, 16));
    m1 = hmax2u(m1, __shfl_xor_sync(0xffffffff, m1, 16));
    m2 = hmax2u(m2, __shfl_xor_sync(0xffffffff, m2, 16));
    m3 = hmax2u(m3, __shfl_xor_sync(0xffffffff, m3, 16));
    if (lane < 8) {
        uint4 o; o.x = m0; o.y = m1; o.z = m2; o.w = m3;
        ((uint4*)(Pl + (size_t)gwarp * F))[sub] = o;
    }
}

// ---------- scalar GEMM body (fp32 f32x2) for the out-GEMMs ------------------
template <int DOUT>
__device__ __forceinline__ void gemm_row(const float4* __restrict__ xr,
                                         const ulonglong2* __restrict__ sW,
                                         ull* acc) {
    #pragma unroll
    for (int k4 = 0; k4 < F / 4; k4++) {
        float4 xv = __ldg(&xr[k4]);
        float xs[4] = {xv.x, xv.y, xv.z, xv.w};
        #pragma unroll
        for (int kk = 0; kk < 4; kk++) {
            int k = k4 * 4 + kk;
            ull xk = pack2(xs[kk]);
            #pragma unroll
            for (int j4 = 0; j4 < DOUT / 4; j4++) {
                ulonglong2 w = sW[k * (DOUT / 4) + j4];
                ffma2(acc[2 * j4 + 0], xk, w.x);
                ffma2(acc[2 * j4 + 1], xk, w.y);
            }
        }
    }
}

// ------- GEMM: Y[N,DOUT] = act(X@Ws + PL(fp16)@Wn + b) -----------------------
template <int DOUT, int ACT>
__global__ __launch_bounds__(256) void gemm_out_kernel(
        const float* __restrict__ X, const __half* __restrict__ PL,
        const float* __restrict__ Ws, const float* __restrict__ Wn,
        const float* __restrict__ b, float* __restrict__ Y) {
    __shared__ ulonglong2 sWs[F * DOUT / 4];
    __shared__ ulonglong2 sWn[F * DOUT / 4];
    __shared__ ull sb[DOUT / 2];
    int t = threadIdx.x;
    const ulonglong2* Ws2 = (const ulonglong2*)Ws;
    const ulonglong2* Wn2 = (const ulonglong2*)Wn;
    for (int i = t; i < F * DOUT / 4; i += 256) { sWs[i] = Ws2[i]; sWn[i] = Wn2[i]; }
    if (t < DOUT / 2) sb[t] = ((const ull*)b)[t];
    __syncthreads();

    int r = blockIdx.x * 256 + t;
    if (r >= N_NODES) return;

    ull acc[DOUT / 2];
    #pragma unroll
    for (int j = 0; j < DOUT / 2; j++) acc[j] = sb[j];

    gemm_row<DOUT>((const float4*)(X + (size_t)r * F), sWs, acc);

    const uint4* pr = (const uint4*)(PL + (size_t)r * F);
    #pragma unroll
    for (int j8 = 0; j8 < F / 8; j8++) {
        uint4 v = __ldg(&pr[j8]);
        unsigned hw[4] = {v.x, v.y, v.z, v.w};
        #pragma unroll
        for (int q = 0; q < 4; q++) {
            float2 f = __half22float2(*reinterpret_cast<__half2*>(&hw[q]));
            int k0 = j8 * 8 + 2 * q;
            ull xa = pack2(f.x);
            ull xb = pack2(f.y);
            #pragma unroll
            for (int j4 = 0; j4 < DOUT / 4; j4++) {
                ulonglong2 wv = sWn[k0 * (DOUT / 4) + j4];
                ffma2(acc[2 * j4 + 0], xa, wv.x);
                ffma2(acc[2 * j4 + 1], xa, wv.y);
            }
            #pragma unroll
            for (int j4 = 0; j4 < DOUT / 4; j4++) {
                ulonglong2 wv = sWn[(k0 + 1) * (DOUT / 4) + j4];
                ffma2(acc[2 * j4 + 0], xb, wv.x);
                ffma2(acc[2 * j4 + 1], xb, wv.y);
            }
        }
    }
    float4* yr = (float4*)(Y + (size_t)r * DOUT);
    #pragma unroll
    for (int j4 = 0; j4 < DOUT / 4; j4++) {
        float2 v0 = unpack2(acc[2 * j4 + 0]);
        float2 v1 = unpack2(acc[2 * j4 + 1]);
        float a0 = v0.x, a1 = v0.y, a2 = v1.x, a3 = v1.y;
        if (ACT == 1) {
            a0 = (a0 >= 0.f) ? a0 : NEG_SLOPE * a0;
            a1 = (a1 >= 0.f) ? a1 : NEG_SLOPE * a1;
            a2 = (a2 >= 0.f) ? a2 : NEG_SLOPE * a2;
            a3 = (a3 >= 0.f) ? a3 : NEG_SLOPE * a3;
        }
        float4 o; o.x = a0; o.y = a1; o.z = a2; o.w = a3;
        yr[j4] = o;
    }
}

// ---------------- launch -----------------------------------------------------
extern "C" void kernel_launch(void* const* d_in, const int* in_sizes, int n_in,
                              void* d_out, int out_size) {
    const float* in_feat = (const float*)d_in[0];
    const int*   src     = (const int*)d_in[1];
    const int*   dst     = (const int*)d_in[2];
    const float* W_pool1 = (const float*)d_in[3];
    const float* b_pool1 = (const float*)d_in[4];
    const float* W_self1 = (const float*)d_in[5];
    const float* W_neigh1= (const float*)d_in[6];
    const float* bias1   = (const float*)d_in[7];
    const float* W_pool2 = (const float*)d_in[8];
    const float* b_pool2 = (const float*)d_in[9];
    const float* W_self2 = (const float*)d_in[10];
    const float* W_neigh2= (const float*)d_in[11];
    const float* bias2   = (const float*)d_in[12];
    float* out = (float*)d_out;

    __half *dP, *dPl; float* dH;
    cudaGetSymbolAddress((void**)&dP, g_P);
    cudaGetSymbolAddress((void**)&dPl, g_Pl);
    cudaGetSymbolAddress((void**)&dH, g_H);

    const int POOLB = (N_NODES * 32 + 255) / 256;

    // K1: flag reset + histogram + layer-1 pool GEMM (tf32 tensor cores)
    hist_gemm_kernel<<<EB4 + NB256, 256>>>((const int4*)dst,
                                           in_feat, W_pool1, b_pool1, dP);
    // K2: single-pass scan
    scan_kernel<<<SCAN_NB, SCAN_BLK>>>();
    // K3: CSR fill
    fill_csr_kernel<<<EB4, 256>>>((const int4*)src, (const int4*)dst);
    // K4: layer-1 pool
    pool_kernel<<<POOLB, 256>>>(dP, dPl);
    // K5: H = leaky(X@Ws1 + Pl@Wn1 + b1)
    gemm_out_kernel<64, 1><<<NB256, 256>>>(in_feat, dPl, W_self1, W_neigh1, bias1, dH);
    // K6: P = relu(H@Wp2 + bp2) (tf32 tensor cores)
    gemm_pool_kernel<<<NB256, 256>>>(dH, W_pool2, b_pool2, dP);
    // K7: layer-2 pool
    pool_kernel<<<POOLB, 256>>>(dP, dPl);
    // K8: out = H@Ws2 + Pl@Wn2 + b2
    gemm_out_kernel<16, 0><<<NB256, 256>>>(dH, dPl, W_self2, W_neigh2, bias2, out);
}

// round 10
// speedup vs baseline: 1.4826x; 1.2746x over previous
#include <cuda_runtime.h>
#include <cuda_fp16.h>
#include <cuda_bf16.h>

#define N_NODES 100000
#define N_EDGES 1600000
#define F 64
#define NCLS 16
#define NEG_SLOPE 0.01f

#define SCAN_BLK 1024
#define SCAN_NB ((N_NODES + SCAN_BLK - 1) / SCAN_BLK)   // 98

#define EB4   ((N_EDGES / 4 + 255) / 256)   // 1563 edge blocks
#define NB256 ((N_NODES + 255) / 256)       // 391 node blocks
#define WSTRIDE 72                          // smem W stride for N=64 tiles

typedef unsigned long long ull;

// ---------------- scratch (device globals; zero at module load) --------------
__device__ int    g_deg[N_NODES];
__device__ int    g_off[N_NODES + 1];
__device__ int    g_cursor[N_NODES];
__device__ int    g_csr[N_EDGES];
__device__ int    g_scan_incl[SCAN_NB];
__device__ int    g_scan_flag[SCAN_NB];
__device__ __half g_P[(size_t)N_NODES * F];
__device__ __half g_Pl[(size_t)N_NODES * F];
__device__ float  g_H[(size_t)N_NODES * F];

// ---------------- helpers ----------------------------------------------------
__device__ __forceinline__ unsigned hmax2u(unsigned a, unsigned b) {
    __half2 r = __hmax2(*reinterpret_cast<__half2*>(&a),
                        *reinterpret_cast<__half2*>(&b));
    return *reinterpret_cast<unsigned*>(&r);
}
__device__ __forceinline__ unsigned f2tf32(float f) {
    unsigned u; asm("cvt.rna.tf32.f32 %0, %1;" : "=r"(u) : "f"(f)); return u;
}
__device__ __forceinline__ void mma_tf32(float* d, const unsigned* a,
                                         unsigned b0, unsigned b1) {
    asm volatile(
        "mma.sync.aligned.m16n8k8.row.col.f32.tf32.tf32.f32 "
        "{%0,%1,%2,%3}, {%4,%5,%6,%7}, {%8,%9}, {%0,%1,%2,%3};"
        : "+f"(d[0]), "+f"(d[1]), "+f"(d[2]), "+f"(d[3])
        : "r"(a[0]), "r"(a[1]), "r"(a[2]), "r"(a[3]), "r"(b0), "r"(b1));
}

// ---- tf32 pool GEMM body: P[256 rows] = relu(X @ W + b) -> fp16 -------------
__device__ __forceinline__ void gemm_pool_tf32_body(
        const float* __restrict__ X, const unsigned* __restrict__ sWt,
        const float* __restrict__ sbias, __half* __restrict__ Y, int rowbase) {
    int lane = threadIdx.x & 31;
    int warp = threadIdx.x >> 5;
    int g = lane >> 2;
    int t4 = lane & 3;
    int wbase = rowbase + warp * 32;
    const int NMAX = N_NODES - 1;

    int r0a = min(wbase + g,      NMAX), r0b = min(wbase + g + 8,  NMAX);
    int r1a = min(wbase + 16 + g, NMAX), r1b = min(wbase + 24 + g, NMAX);

    float acc[2][8][4];
    #pragma unroll
    for (int T = 0; T < 2; T++)
        #pragma unroll
        for (int nf = 0; nf < 8; nf++) {
            float bb0 = sbias[8 * nf + 2 * t4];
            float bb1 = sbias[8 * nf + 2 * t4 + 1];
            acc[T][nf][0] = bb0; acc[T][nf][1] = bb1;
            acc[T][nf][2] = bb0; acc[T][nf][3] = bb1;
        }

    #pragma unroll
    for (int kf = 0; kf < 8; kf++) {
        int k0 = 8 * kf + t4;
        unsigned a[2][4];
        a[0][0] = f2tf32(__ldg(&X[(size_t)r0a * F + k0]));
        a[0][1] = f2tf32(__ldg(&X[(size_t)r0b * F + k0]));
        a[0][2] = f2tf32(__ldg(&X[(size_t)r0a * F + k0 + 4]));
        a[0][3] = f2tf32(__ldg(&X[(size_t)r0b * F + k0 + 4]));
        a[1][0] = f2tf32(__ldg(&X[(size_t)r1a * F + k0]));
        a[1][1] = f2tf32(__ldg(&X[(size_t)r1b * F + k0]));
        a[1][2] = f2tf32(__ldg(&X[(size_t)r1a * F + k0 + 4]));
        a[1][3] = f2tf32(__ldg(&X[(size_t)r1b * F + k0 + 4]));
        #pragma unroll
        for (int nf = 0; nf < 8; nf++) {
            unsigned b0 = sWt[(8 * kf + t4) * WSTRIDE + 8 * nf + g];
            unsigned b1 = sWt[(8 * kf + t4 + 4) * WSTRIDE + 8 * nf + g];
            mma_tf32(acc[0][nf], a[0], b0, b1);
            mma_tf32(acc[1][nf], a[1], b0, b1);
        }
    }

    #pragma unroll
    for (int T = 0; T < 2; T++) {
        int ra = wbase + 16 * T + g;
        int rb = ra + 8;
        #pragma unroll
        for (int nf = 0; nf < 8; nf++) {
            int col = 8 * nf + 2 * t4;
            if (ra < N_NODES) {
                __half2 h = __floats2half2_rn(fmaxf(acc[T][nf][0], 0.f),
                                              fmaxf(acc[T][nf][1], 0.f));
                *(__half2*)(Y + (size_t)ra * F + col) = h;
            }
            if (rb < N_NODES) {
                __half2 h = __floats2half2_rn(fmaxf(acc[T][nf][2], 0.f),
                                              fmaxf(acc[T][nf][3], 0.f));
                *(__half2*)(Y + (size_t)rb * F + col) = h;
            }
        }
    }
}

__device__ __forceinline__ void stage_w_tf32(
        const float* __restrict__ W, const float* __restrict__ b,
        unsigned* sWt, float* sbias) {
    int t = threadIdx.x;
    for (int i = t; i < F * F; i += 256) {
        int k = i >> 6, n = i & 63;
        sWt[k * WSTRIDE + n] = f2tf32(__ldg(&W[i]));
    }
    if (t < F) sbias[t] = b[t];
}

// ------- K1: merged edge histogram + layer-1 pool GEMM (tf32) ----------------
__global__ __launch_bounds__(256) void hist_gemm_kernel(
        const int4* __restrict__ dst4,
        const float* __restrict__ X, const float* __restrict__ W,
        const float* __restrict__ b, __half* __restrict__ Y) {
    __shared__ unsigned sWt[F * WSTRIDE];
    __shared__ float sbias[F];
    int t = threadIdx.x;

    if (blockIdx.x < EB4) {
        if (blockIdx.x == 0 && t < SCAN_NB) g_scan_flag[t] = 0;
        int i = blockIdx.x * 256 + t;
        if (i < N_EDGES / 4) {
            int4 d = __ldg(&dst4[i]);
            atomicAdd(&g_deg[d.x], 1);
            atomicAdd(&g_deg[d.y], 1);
            atomicAdd(&g_deg[d.z], 1);
            atomicAdd(&g_deg[d.w], 1);
        }
        return;
    }

    stage_w_tf32(W, b, sWt, sbias);
    __syncthreads();
    gemm_pool_tf32_body(X, sWt, sbias, Y, (blockIdx.x - EB4) * 256);
}

// ---------------- layer-2 pool GEMM (tf32) -----------------------------------
__global__ __launch_bounds__(256) void gemm_pool_kernel(
        const float* __restrict__ X, const float* __restrict__ W,
        const float* __restrict__ b, __half* __restrict__ Y) {
    __shared__ unsigned sWt[F * WSTRIDE];
    __shared__ float sbias[F];
    stage_w_tf32(W, b, sWt, sbias);
    __syncthreads();
    gemm_pool_tf32_body(X, sWt, sbias, Y, blockIdx.x * 256);
}

// ------- single-kernel scan: decoupled lookback ------------------------------
__global__ __launch_bounds__(SCAN_BLK) void scan_kernel() {
    __shared__ int s[SCAN_BLK];
    __shared__ int s_carry;
    int t = threadIdx.x;
    int b = blockIdx.x;
    int idx = b * SCAN_BLK + t;
    int val = 0;
    if (idx < N_NODES) { val = g_deg[idx]; g_deg[idx] = 0; }
    s[t] = val;
    __syncthreads();
    #pragma unroll
    for (int o = 1; o < SCAN_BLK; o <<= 1) {
        int x = (t >= o) ? s[t - o] : 0;
        __syncthreads();
        s[t] += x;
        __syncthreads();
    }
    int incl = s[t];
    if (t == SCAN_BLK - 1) {
        g_scan_incl[b] = incl;
        __threadfence();
        atomicExch(&g_scan_flag[b], 1);
    }
    if (t < 32) {
        int c = 0;
        for (int i = t; i < b; i += 32) {
            while (atomicAdd(&g_scan_flag[i], 0) == 0) { __nanosleep(40); }
            __threadfence();
            c += g_scan_incl[i];
        }
        #pragma unroll
        for (int o = 16; o; o >>= 1) c += __shfl_down_sync(0xffffffff, c, o);
        if (t == 0) s_carry = c;
    }
    __syncthreads();
    int off = s_carry + incl - val;
    if (idx < N_NODES) {
        g_off[idx] = off;
        g_cursor[idx] = off;
    }
    if (idx == 0) g_off[N_NODES] = N_EDGES;
}

__global__ void fill_csr_kernel(const int4* __restrict__ src4,
                                const int4* __restrict__ dst4) {
    int i = blockIdx.x * blockDim.x + threadIdx.x;
    if (i < N_EDGES / 4) {
        int4 s = __ldg(&src4[i]);
        int4 d = __ldg(&dst4[i]);
        g_csr[atomicAdd(&g_cursor[d.x], 1)] = s.x;
        g_csr[atomicAdd(&g_cursor[d.y], 1)] = s.y;
        g_csr[atomicAdd(&g_cursor[d.z], 1)] = s.z;
        g_csr[atomicAdd(&g_cursor[d.w], 1)] = s.w;
    }
}

// ---------------- segment max pool: warp per node ----------------------------
__global__ __launch_bounds__(256) void pool_kernel(const __half* __restrict__ P,
                                                   __half* __restrict__ Pl) {
    int gwarp = (blockIdx.x * 256 + threadIdx.x) >> 5;
    int lane  = threadIdx.x & 31;
    if (gwarp >= N_NODES) return;
    int grp = lane >> 3;
    int sub = lane & 7;
    int s0 = g_off[gwarp];
    int s1 = g_off[gwarp + 1];
    unsigned m0 = 0, m1 = 0, m2 = 0, m3 = 0;
    const uint4* Prow = (const uint4*)P;

    if (s0 < s1) {
        int last = s1 - 1;
        for (int e = s0; e < s1; e += 8) {
            int ea = min(e + grp, last);
            int eb = min(e + 4 + grp, last);
            int ia = g_csr[ea];
            int ib = g_csr[eb];
            uint4 va = __ldg(&Prow[ia * 8 + sub]);
            uint4 vb = __ldg(&Prow[ib * 8 + sub]);
            m0 = hmax2u(m0, hmax2u(va.x, vb.x));
            m1 = hmax2u(m1, hmax2u(va.y, vb.y));
            m2 = hmax2u(m2, hmax2u(va.z, vb.z));
            m3 = hmax2u(m3, hmax2u(va.w, vb.w));
        }
    }
    m0 = hmax2u(m0, __shfl_xor_sync(0xffffffff, m0, 8));
    m1 = hmax2u(m1, __shfl_xor_sync(0xffffffff, m1, 8));
    m2 = hmax2u(m2, __shfl_xor_sync(0xffffffff, m2, 8));
    m3 = hmax2u(m3, __shfl_xor_sync(0xffffffff, m3, 8));
    m0 = hmax2u(m0, __shfl_xor_sync(0xffffffff, m0, 16));
    m1 = hmax2u(m1, __shfl_xor_sync(0xffffffff, m1, 16));
    m2 = hmax2u(m2, __shfl_xor_sync(0xffffffff, m2, 16));
    m3 = hmax2u(m3, __shfl_xor_sync(0xffffffff, m3, 16));
    if (lane < 8) {
        uint4 o; o.x = m0; o.y = m1; o.z = m2; o.w = m3;
        ((uint4*)(Pl + (size_t)gwarp * F))[sub] = o;
    }
}

// ------- tf32 out-GEMM: Y[N,DOUT] = act([X | PL] @ [Ws;Wn] + b), K=128 -------
// SW = smem stride for the stacked weight tile (bank-conflict-free pad).
template <int DOUT, int ACT, int SW>
__device__ __forceinline__ void gemm_out_tf32_body(
        const float* __restrict__ X, const __half* __restrict__ PL,
        const unsigned* __restrict__ sWt, const float* __restrict__ sbias,
        float* __restrict__ Y, int rowbase) {
    const int NF = DOUT / 8;
    int lane = threadIdx.x & 31;
    int warp = threadIdx.x >> 5;
    int g = lane >> 2;
    int t4 = lane & 3;
    int wbase = rowbase + warp * 32;
    const int NMAX = N_NODES - 1;

    int r0a = min(wbase + g,      NMAX), r0b = min(wbase + g + 8,  NMAX);
    int r1a = min(wbase + 16 + g, NMAX), r1b = min(wbase + 24 + g, NMAX);

    float acc[2][NF][4];
    #pragma unroll
    for (int T = 0; T < 2; T++)
        #pragma unroll
        for (int nf = 0; nf < NF; nf++) {
            float bb0 = sbias[8 * nf + 2 * t4];
            float bb1 = sbias[8 * nf + 2 * t4 + 1];
            acc[T][nf][0] = bb0; acc[T][nf][1] = bb1;
            acc[T][nf][2] = bb0; acc[T][nf][3] = bb1;
        }

    // self term: kf 0..7 from X (fp32)
    #pragma unroll
    for (int kf = 0; kf < 8; kf++) {
        int k0 = 8 * kf + t4;
        unsigned a[2][4];
        a[0][0] = f2tf32(__ldg(&X[(size_t)r0a * F + k0]));
        a[0][1] = f2tf32(__ldg(&X[(size_t)r0b * F + k0]));
        a[0][2] = f2tf32(__ldg(&X[(size_t)r0a * F + k0 + 4]));
        a[0][3] = f2tf32(__ldg(&X[(size_t)r0b * F + k0 + 4]));
        a[1][0] = f2tf32(__ldg(&X[(size_t)r1a * F + k0]));
        a[1][1] = f2tf32(__ldg(&X[(size_t)r1b * F + k0]));
        a[1][2] = f2tf32(__ldg(&X[(size_t)r1a * F + k0 + 4]));
        a[1][3] = f2tf32(__ldg(&X[(size_t)r1b * F + k0 + 4]));
        #pragma unroll
        for (int nf = 0; nf < NF; nf++) {
            unsigned b0 = sWt[(8 * kf + t4) * SW + 8 * nf + g];
            unsigned b1 = sWt[(8 * kf + t4 + 4) * SW + 8 * nf + g];
            mma_tf32(acc[0][nf], a[0], b0, b1);
            mma_tf32(acc[1][nf], a[1], b0, b1);
        }
    }
    // neighbor term: kf 8..15 from PL (fp16 -> tf32)
    #pragma unroll
    for (int kf = 0; kf < 8; kf++) {
        int k0 = 8 * kf + t4;
        unsigned a[2][4];
        a[0][0] = f2tf32(__half2float(__ldg(&PL[(size_t)r0a * F + k0])));
        a[0][1] = f2tf32(__half2float(__ldg(&PL[(size_t)r0b * F + k0])));
        a[0][2] = f2tf32(__half2float(__ldg(&PL[(size_t)r0a * F + k0 + 4])));
        a[0][3] = f2tf32(__half2float(__ldg(&PL[(size_t)r0b * F + k0 + 4])));
        a[1][0] = f2tf32(__half2float(__ldg(&PL[(size_t)r1a * F + k0])));
        a[1][1] = f2tf32(__half2float(__ldg(&PL[(size_t)r1b * F + k0])));
        a[1][2] = f2tf32(__half2float(__ldg(&PL[(size_t)r1a * F + k0 + 4])));
        a[1][3] = f2tf32(__half2float(__ldg(&PL[(size_t)r1b * F + k0 + 4])));
        #pragma unroll
        for (int nf = 0; nf < NF; nf++) {
            unsigned b0 = sWt[(64 + 8 * kf + t4) * SW + 8 * nf + g];
            unsigned b1 = sWt[(64 + 8 * kf + t4 + 4) * SW + 8 * nf + g];
            mma_tf32(acc[0][nf], a[0], b0, b1);
            mma_tf32(acc[1][nf], a[1], b0, b1);
        }
    }

    // epilogue: activation + fp32 stores
    #pragma unroll
    for (int T = 0; T < 2; T++) {
        int ra = wbase + 16 * T + g;
        int rb = ra + 8;
        #pragma unroll
        for (int nf = 0; nf < NF; nf++) {
            int col = 8 * nf + 2 * t4;
            float v0 = acc[T][nf][0], v1 = acc[T][nf][1];
            float v2 = acc[T][nf][2], v3 = acc[T][nf][3];
            if (ACT == 1) {
                v0 = (v0 >= 0.f) ? v0 : NEG_SLOPE * v0;
                v1 = (v1 >= 0.f) ? v1 : NEG_SLOPE * v1;
                v2 = (v2 >= 0.f) ? v2 : NEG_SLOPE * v2;
                v3 = (v3 >= 0.f) ? v3 : NEG_SLOPE * v3;
            }
            if (ra < N_NODES) {
                float2 o; o.x = v0; o.y = v1;
                *(float2*)(Y + (size_t)ra * DOUT + col) = o;
            }
            if (rb < N_NODES) {
                float2 o; o.x = v2; o.y = v3;
                *(float2*)(Y + (size_t)rb * DOUT + col) = o;
            }
        }
    }
}

template <int DOUT, int SW>
__device__ __forceinline__ void stage_w2_tf32(
        const float* __restrict__ Ws, const float* __restrict__ Wn,
        const float* __restrict__ b, unsigned* sWt, float* sbias) {
    int t = threadIdx.x;
    for (int i = t; i < F * DOUT; i += 256) {
        int k = i / DOUT, n = i % DOUT;
        sWt[k * SW + n]        = f2tf32(__ldg(&Ws[i]));
        sWt[(64 + k) * SW + n] = f2tf32(__ldg(&Wn[i]));
    }
    if (t < DOUT) sbias[t] = b[t];
}

template <int DOUT, int ACT, int SW>
__global__ __launch_bounds__(256) void gemm_out_kernel(
        const float* __restrict__ X, const __half* __restrict__ PL,
        const float* __restrict__ Ws, const float* __restrict__ Wn,
        const float* __restrict__ b, float* __restrict__ Y) {
    __shared__ unsigned sWt[128 * SW];
    __shared__ float sbias[DOUT];
    stage_w2_tf32<DOUT, SW>(Ws, Wn, b, sWt, sbias);
    __syncthreads();
    gemm_out_tf32_body<DOUT, ACT, SW>(X, PL, sWt, sbias, Y, blockIdx.x * 256);
}

// ---------------- launch -----------------------------------------------------
extern "C" void kernel_launch(void* const* d_in, const int* in_sizes, int n_in,
                              void* d_out, int out_size) {
    const float* in_feat = (const float*)d_in[0];
    const int*   src     = (const int*)d_in[1];
    const int*   dst     = (const int*)d_in[2];
    const float* W_pool1 = (const float*)d_in[3];
    const float* b_pool1 = (const float*)d_in[4];
    const float* W_self1 = (const float*)d_in[5];
    const float* W_neigh1= (const float*)d_in[6];
    const float* bias1   = (const float*)d_in[7];
    const float* W_pool2 = (const float*)d_in[8];
    const float* b_pool2 = (const float*)d_in[9];
    const float* W_self2 = (const float*)d_in[10];
    const float* W_neigh2= (const float*)d_in[11];
    const float* bias2   = (const float*)d_in[12];
    float* out = (float*)d_out;

    __half *dP, *dPl; float* dH;
    cudaGetSymbolAddress((void**)&dP, g_P);
    cudaGetSymbolAddress((void**)&dPl, g_Pl);
    cudaGetSymbolAddress((void**)&dH, g_H);

    const int POOLB = (N_NODES * 32 + 255) / 256;

    // K1: flag reset + histogram + layer-1 pool GEMM (tf32)
    hist_gemm_kernel<<<EB4 + NB256, 256>>>((const int4*)dst,
                                           in_feat, W_pool1, b_pool1, dP);
    // K2: single-pass scan
    scan_kernel<<<SCAN_NB, SCAN_BLK>>>();
    // K3: CSR fill
    fill_csr_kernel<<<EB4, 256>>>((const int4*)src, (const int4*)dst);
    // K4: layer-1 pool
    pool_kernel<<<POOLB, 256>>>(dP, dPl);
    // K5: H = leaky(X@Ws1 + Pl@Wn1 + b1)  (tf32, K=128)
    gemm_out_kernel<64, 1, 72><<<NB256, 256>>>(in_feat, dPl, W_self1, W_neigh1,
                                               bias1, dH);
    // K6: P = relu(H@Wp2 + bp2)  (tf32)
    gemm_pool_kernel<<<NB256, 256>>>(dH, W_pool2, b_pool2, dP);
    // K7: layer-2 pool
    pool_kernel<<<POOLB, 256>>>(dP, dPl);
    // K8: out = H@Ws2 + Pl@Wn2 + b2  (tf32, K=128)
    gemm_out_kernel<16, 0, 24><<<NB256, 256>>>(dH, dPl, W_self2, W_neigh2,
                                               bias2, out);
}

// round 11
// speedup vs baseline: 1.5105x; 1.0188x over previous
#include <cuda_runtime.h>
#include <cuda_fp16.h>
#include <cuda_bf16.h>

#define N_NODES 100000
#define N_EDGES 1600000
#define F 64
#define NCLS 16
#define NEG_SLOPE 0.01f

#define SCAN_BLK 1024
#define SCAN_NB ((N_NODES + SCAN_BLK - 1) / SCAN_BLK)   // 98

#define EB4   ((N_EDGES / 4 + 255) / 256)   // 1563 edge blocks
#define NB256 ((N_NODES + 255) / 256)       // 391 node blocks
#define WSTRIDE 72                          // smem W stride for N=64 tiles

typedef unsigned long long ull;

// ---------------- scratch (device globals; zero at module load) --------------
__device__ int    g_deg[N_NODES];
__device__ int    g_off[N_NODES + 1];
__device__ int    g_cursor[N_NODES];
__device__ int    g_csr[N_EDGES];
__device__ int    g_scan_incl[SCAN_NB];
__device__ int    g_scan_flag[SCAN_NB];
__device__ __half g_P[(size_t)N_NODES * F];
__device__ __half g_Pl[(size_t)N_NODES * F];
__device__ float  g_H[(size_t)N_NODES * F];

// ---------------- helpers ----------------------------------------------------
__device__ __forceinline__ unsigned hmax2u(unsigned a, unsigned b) {
    __half2 r = __hmax2(*reinterpret_cast<__half2*>(&a),
                        *reinterpret_cast<__half2*>(&b));
    return *reinterpret_cast<unsigned*>(&r);
}
__device__ __forceinline__ unsigned f2tf32(float f) {
    unsigned u; asm("cvt.rna.tf32.f32 %0, %1;" : "=r"(u) : "f"(f)); return u;
}
__device__ __forceinline__ void mma_tf32(float* d, const unsigned* a,
                                         unsigned b0, unsigned b1) {
    asm volatile(
        "mma.sync.aligned.m16n8k8.row.col.f32.tf32.tf32.f32 "
        "{%0,%1,%2,%3}, {%4,%5,%6,%7}, {%8,%9}, {%0,%1,%2,%3};"
        : "+f"(d[0]), "+f"(d[1]), "+f"(d[2]), "+f"(d[3])
        : "r"(a[0]), "r"(a[1]), "r"(a[2]), "r"(a[3]), "r"(b0), "r"(b1));
}

// ---- tf32 pool GEMM body: P[256 rows] = relu(X @ W + b) -> fp16 -------------
__device__ __forceinline__ void gemm_pool_tf32_body(
        const float* __restrict__ X, const unsigned* __restrict__ sWt,
        const float* __restrict__ sbias, __half* __restrict__ Y, int rowbase) {
    int lane = threadIdx.x & 31;
    int warp = threadIdx.x >> 5;
    int g = lane >> 2;
    int t4 = lane & 3;
    int wbase = rowbase + warp * 32;
    const int NMAX = N_NODES - 1;

    int r0a = min(wbase + g,      NMAX), r0b = min(wbase + g + 8,  NMAX);
    int r1a = min(wbase + 16 + g, NMAX), r1b = min(wbase + 24 + g, NMAX);

    float acc[2][8][4];
    #pragma unroll
    for (int T = 0; T < 2; T++)
        #pragma unroll
        for (int nf = 0; nf < 8; nf++) {
            float bb0 = sbias[8 * nf + 2 * t4];
            float bb1 = sbias[8 * nf + 2 * t4 + 1];
            acc[T][nf][0] = bb0; acc[T][nf][1] = bb1;
            acc[T][nf][2] = bb0; acc[T][nf][3] = bb1;
        }

    #pragma unroll
    for (int kf = 0; kf < 8; kf++) {
        int k0 = 8 * kf + t4;
        unsigned a[2][4];
        a[0][0] = f2tf32(__ldg(&X[(size_t)r0a * F + k0]));
        a[0][1] = f2tf32(__ldg(&X[(size_t)r0b * F + k0]));
        a[0][2] = f2tf32(__ldg(&X[(size_t)r0a * F + k0 + 4]));
        a[0][3] = f2tf32(__ldg(&X[(size_t)r0b * F + k0 + 4]));
        a[1][0] = f2tf32(__ldg(&X[(size_t)r1a * F + k0]));
        a[1][1] = f2tf32(__ldg(&X[(size_t)r1b * F + k0]));
        a[1][2] = f2tf32(__ldg(&X[(size_t)r1a * F + k0 + 4]));
        a[1][3] = f2tf32(__ldg(&X[(size_t)r1b * F + k0 + 4]));
        #pragma unroll
        for (int nf = 0; nf < 8; nf++) {
            unsigned b0 = sWt[(8 * kf + t4) * WSTRIDE + 8 * nf + g];
            unsigned b1 = sWt[(8 * kf + t4 + 4) * WSTRIDE + 8 * nf + g];
            mma_tf32(acc[0][nf], a[0], b0, b1);
            mma_tf32(acc[1][nf], a[1], b0, b1);
        }
    }

    #pragma unroll
    for (int T = 0; T < 2; T++) {
        int ra = wbase + 16 * T + g;
        int rb = ra + 8;
        #pragma unroll
        for (int nf = 0; nf < 8; nf++) {
            int col = 8 * nf + 2 * t4;
            if (ra < N_NODES) {
                __half2 h = __floats2half2_rn(fmaxf(acc[T][nf][0], 0.f),
                                              fmaxf(acc[T][nf][1], 0.f));
                *(__half2*)(Y + (size_t)ra * F + col) = h;
            }
            if (rb < N_NODES) {
                __half2 h = __floats2half2_rn(fmaxf(acc[T][nf][2], 0.f),
                                              fmaxf(acc[T][nf][3], 0.f));
                *(__half2*)(Y + (size_t)rb * F + col) = h;
            }
        }
    }
}

__device__ __forceinline__ void stage_w_tf32(
        const float* __restrict__ W, const float* __restrict__ b,
        unsigned* sWt, float* sbias) {
    int t = threadIdx.x;
    for (int i = t; i < F * F; i += 256) {
        int k = i >> 6, n = i & 63;
        sWt[k * WSTRIDE + n] = f2tf32(__ldg(&W[i]));
    }
    if (t < F) sbias[t] = b[t];
}

// ------- K1: merged edge histogram + layer-1 pool GEMM (tf32) ----------------
__global__ __launch_bounds__(256) void hist_gemm_kernel(
        const int4* __restrict__ dst4,
        const float* __restrict__ X, const float* __restrict__ W,
        const float* __restrict__ b, __half* __restrict__ Y) {
    __shared__ unsigned sWt[F * WSTRIDE];
    __shared__ float sbias[F];
    int t = threadIdx.x;

    if (blockIdx.x < EB4) {
        if (blockIdx.x == 0 && t < SCAN_NB) g_scan_flag[t] = 0;
        int i = blockIdx.x * 256 + t;
        if (i < N_EDGES / 4) {
            int4 d = __ldg(&dst4[i]);
            atomicAdd(&g_deg[d.x], 1);
            atomicAdd(&g_deg[d.y], 1);
            atomicAdd(&g_deg[d.z], 1);
            atomicAdd(&g_deg[d.w], 1);
        }
        return;
    }

    stage_w_tf32(W, b, sWt, sbias);
    __syncthreads();
    gemm_pool_tf32_body(X, sWt, sbias, Y, (blockIdx.x - EB4) * 256);
}

// ---------------- layer-2 pool GEMM (tf32) -----------------------------------
__global__ __launch_bounds__(256) void gemm_pool_kernel(
        const float* __restrict__ X, const float* __restrict__ W,
        const float* __restrict__ b, __half* __restrict__ Y) {
    __shared__ unsigned sWt[F * WSTRIDE];
    __shared__ float sbias[F];
    stage_w_tf32(W, b, sWt, sbias);
    __syncthreads();
    gemm_pool_tf32_body(X, sWt, sbias, Y, blockIdx.x * 256);
}

// ------- single-kernel scan: decoupled lookback ------------------------------
__global__ __launch_bounds__(SCAN_BLK) void scan_kernel() {
    __shared__ int s[SCAN_BLK];
    __shared__ int s_carry;
    int t = threadIdx.x;
    int b = blockIdx.x;
    int idx = b * SCAN_BLK + t;
    int val = 0;
    if (idx < N_NODES) { val = g_deg[idx]; g_deg[idx] = 0; }
    s[t] = val;
    __syncthreads();
    #pragma unroll
    for (int o = 1; o < SCAN_BLK; o <<= 1) {
        int x = (t >= o) ? s[t - o] : 0;
        __syncthreads();
        s[t] += x;
        __syncthreads();
    }
    int incl = s[t];
    if (t == SCAN_BLK - 1) {
        g_scan_incl[b] = incl;
        __threadfence();
        atomicExch(&g_scan_flag[b], 1);
    }
    if (t < 32) {
        int c = 0;
        for (int i = t; i < b; i += 32) {
            while (atomicAdd(&g_scan_flag[i], 0) == 0) { __nanosleep(40); }
            __threadfence();
            c += g_scan_incl[i];
        }
        #pragma unroll
        for (int o = 16; o; o >>= 1) c += __shfl_down_sync(0xffffffff, c, o);
        if (t == 0) s_carry = c;
    }
    __syncthreads();
    int off = s_carry + incl - val;
    if (idx < N_NODES) {
        g_off[idx] = off;
        g_cursor[idx] = off;
    }
    if (idx == 0) g_off[N_NODES] = N_EDGES;
}

__global__ void fill_csr_kernel(const int4* __restrict__ src4,
                                const int4* __restrict__ dst4) {
    int i = blockIdx.x * blockDim.x + threadIdx.x;
    if (i < N_EDGES / 4) {
        int4 s = __ldg(&src4[i]);
        int4 d = __ldg(&dst4[i]);
        g_csr[atomicAdd(&g_cursor[d.x], 1)] = s.x;
        g_csr[atomicAdd(&g_cursor[d.y], 1)] = s.y;
        g_csr[atomicAdd(&g_cursor[d.z], 1)] = s.z;
        g_csr[atomicAdd(&g_cursor[d.w], 1)] = s.w;
    }
}

// ------- segment max pool v3: 8-lane group per node, 4 nodes/warp ------------
// sub = lane&7 owns a 16B chunk of the 128B feature row; grp = lane>>3 selects
// the node. No cross-lane reduction needed: each group's running max IS the
// final row. Unroll 4 edges/iteration (4 LDG.128 in flight per lane); tail
// edges handled by index clamp (max is idempotent). Empty segments write 0.
__global__ __launch_bounds__(256) void pool_kernel(const __half* __restrict__ P,
                                                   __half* __restrict__ Pl) {
    int warp_g = (blockIdx.x * 256 + threadIdx.x) >> 5;
    int lane   = threadIdx.x & 31;
    int grp = lane >> 3;
    int sub = lane & 7;
    int node = warp_g * 4 + grp;
    if (node >= N_NODES) return;

    int s0 = g_off[node];
    int s1 = g_off[node + 1];
    unsigned m0 = 0, m1 = 0, m2 = 0, m3 = 0;
    const uint4* Prow = (const uint4*)P;

    if (s0 < s1) {
        int last = s1 - 1;
        for (int e = s0; e < s1; e += 4) {
            int e1 = min(e + 1, last), e2 = min(e + 2, last), e3 = min(e + 3, last);
            int i0 = g_csr[e];
            int i1 = g_csr[e1];
            int i2 = g_csr[e2];
            int i3 = g_csr[e3];
            uint4 v0 = __ldg(&Prow[i0 * 8 + sub]);
            uint4 v1 = __ldg(&Prow[i1 * 8 + sub]);
            uint4 v2 = __ldg(&Prow[i2 * 8 + sub]);
            uint4 v3 = __ldg(&Prow[i3 * 8 + sub]);
            m0 = hmax2u(m0, hmax2u(hmax2u(v0.x, v1.x), hmax2u(v2.x, v3.x)));
            m1 = hmax2u(m1, hmax2u(hmax2u(v0.y, v1.y), hmax2u(v2.y, v3.y)));
            m2 = hmax2u(m2, hmax2u(hmax2u(v0.z, v1.z), hmax2u(v2.z, v3.z)));
            m3 = hmax2u(m3, hmax2u(hmax2u(v0.w, v1.w), hmax2u(v2.w, v3.w)));
        }
    }
    uint4 o; o.x = m0; o.y = m1; o.z = m2; o.w = m3;
    ((uint4*)(Pl + (size_t)node * F))[sub] = o;
}

// ------- tf32 out-GEMM: Y[N,DOUT] = act([X | PL] @ [Ws;Wn] + b), K=128 -------
template <int DOUT, int ACT, int SW>
__device__ __forceinline__ void gemm_out_tf32_body(
        const float* __restrict__ X, const __half* __restrict__ PL,
        const unsigned* __restrict__ sWt, const float* __restrict__ sbias,
        float* __restrict__ Y, int rowbase) {
    const int NF = DOUT / 8;
    int lane = threadIdx.x & 31;
    int warp = threadIdx.x >> 5;
    int g = lane >> 2;
    int t4 = lane & 3;
    int wbase = rowbase + warp * 32;
    const int NMAX = N_NODES - 1;

    int r0a = min(wbase + g,      NMAX), r0b = min(wbase + g + 8,  NMAX);
    int r1a = min(wbase + 16 + g, NMAX), r1b = min(wbase + 24 + g, NMAX);

    float acc[2][NF][4];
    #pragma unroll
    for (int T = 0; T < 2; T++)
        #pragma unroll
        for (int nf = 0; nf < NF; nf++) {
            float bb0 = sbias[8 * nf + 2 * t4];
            float bb1 = sbias[8 * nf + 2 * t4 + 1];
            acc[T][nf][0] = bb0; acc[T][nf][1] = bb1;
            acc[T][nf][2] = bb0; acc[T][nf][3] = bb1;
        }

    // self term: kf 0..7 from X (fp32)
    #pragma unroll
    for (int kf = 0; kf < 8; kf++) {
        int k0 = 8 * kf + t4;
        unsigned a[2][4];
        a[0][0] = f2tf32(__ldg(&X[(size_t)r0a * F + k0]));
        a[0][1] = f2tf32(__ldg(&X[(size_t)r0b * F + k0]));
        a[0][2] = f2tf32(__ldg(&X[(size_t)r0a * F + k0 + 4]));
        a[0][3] = f2tf32(__ldg(&X[(size_t)r0b * F + k0 + 4]));
        a[1][0] = f2tf32(__ldg(&X[(size_t)r1a * F + k0]));
        a[1][1] = f2tf32(__ldg(&X[(size_t)r1b * F + k0]));
        a[1][2] = f2tf32(__ldg(&X[(size_t)r1a * F + k0 + 4]));
        a[1][3] = f2tf32(__ldg(&X[(size_t)r1b * F + k0 + 4]));
        #pragma unroll
        for (int nf = 0; nf < NF; nf++) {
            unsigned b0 = sWt[(8 * kf + t4) * SW + 8 * nf + g];
            unsigned b1 = sWt[(8 * kf + t4 + 4) * SW + 8 * nf + g];
            mma_tf32(acc[0][nf], a[0], b0, b1);
            mma_tf32(acc[1][nf], a[1], b0, b1);
        }
    }
    // neighbor term: kf 8..15 from PL (fp16 -> tf32)
    #pragma unroll
    for (int kf = 0; kf < 8; kf++) {
        int k0 = 8 * kf + t4;
        unsigned a[2][4];
        a[0][0] = f2tf32(__half2float(__ldg(&PL[(size_t)r0a * F + k0])));
        a[0][1] = f2tf32(__half2float(__ldg(&PL[(size_t)r0b * F + k0])));
        a[0][2] = f2tf32(__half2float(__ldg(&PL[(size_t)r0a * F + k0 + 4])));
        a[0][3] = f2tf32(__half2float(__ldg(&PL[(size_t)r0b * F + k0 + 4])));
        a[1][0] = f2tf32(__half2float(__ldg(&PL[(size_t)r1a * F + k0])));
        a[1][1] = f2tf32(__half2float(__ldg(&PL[(size_t)r1b * F + k0])));
        a[1][2] = f2tf32(__half2float(__ldg(&PL[(size_t)r1a * F + k0 + 4])));
        a[1][3] = f2tf32(__half2float(__ldg(&PL[(size_t)r1b * F + k0 + 4])));
        #pragma unroll
        for (int nf = 0; nf < NF; nf++) {
            unsigned b0 = sWt[(64 + 8 * kf + t4) * SW + 8 * nf + g];
            unsigned b1 = sWt[(64 + 8 * kf + t4 + 4) * SW + 8 * nf + g];
            mma_tf32(acc[0][nf], a[0], b0, b1);
            mma_tf32(acc[1][nf], a[1], b0, b1);
        }
    }

    #pragma unroll
    for (int T = 0; T < 2; T++) {
        int ra = wbase + 16 * T + g;
        int rb = ra + 8;
        #pragma unroll
        for (int nf = 0; nf < NF; nf++) {
            int col = 8 * nf + 2 * t4;
            float v0 = acc[T][nf][0], v1 = acc[T][nf][1];
            float v2 = acc[T][nf][2], v3 = acc[T][nf][3];
            if (ACT == 1) {
                v0 = (v0 >= 0.f) ? v0 : NEG_SLOPE * v0;
                v1 = (v1 >= 0.f) ? v1 : NEG_SLOPE * v1;
                v2 = (v2 >= 0.f) ? v2 : NEG_SLOPE * v2;
                v3 = (v3 >= 0.f) ? v3 : NEG_SLOPE * v3;
            }
            if (ra < N_NODES) {
                float2 o; o.x = v0; o.y = v1;
                *(float2*)(Y + (size_t)ra * DOUT + col) = o;
            }
            if (rb < N_NODES) {
                float2 o; o.x = v2; o.y = v3;
                *(float2*)(Y + (size_t)rb * DOUT + col) = o;
            }
        }
    }
}

template <int DOUT, int SW>
__device__ __forceinline__ void stage_w2_tf32(
        const float* __restrict__ Ws, const float* __restrict__ Wn,
        const float* __restrict__ b, unsigned* sWt, float* sbias) {
    int t = threadIdx.x;
    for (int i = t; i < F * DOUT; i += 256) {
        int k = i / DOUT, n = i % DOUT;
        sWt[k * SW + n]        = f2tf32(__ldg(&Ws[i]));
        sWt[(64 + k) * SW + n] = f2tf32(__ldg(&Wn[i]));
    }
    if (t < DOUT) sbias[t] = b[t];
}

template <int DOUT, int ACT, int SW>
__global__ __launch_bounds__(256) void gemm_out_kernel(
        const float* __restrict__ X, const __half* __restrict__ PL,
        const float* __restrict__ Ws, const float* __restrict__ Wn,
        const float* __restrict__ b, float* __restrict__ Y) {
    __shared__ unsigned sWt[128 * SW];
    __shared__ float sbias[DOUT];
    stage_w2_tf32<DOUT, SW>(Ws, Wn, b, sWt, sbias);
    __syncthreads();
    gemm_out_tf32_body<DOUT, ACT, SW>(X, PL, sWt, sbias, Y, blockIdx.x * 256);
}

// ---------------- launch -----------------------------------------------------
extern "C" void kernel_launch(void* const* d_in, const int* in_sizes, int n_in,
                              void* d_out, int out_size) {
    const float* in_feat = (const float*)d_in[0];
    const int*   src     = (const int*)d_in[1];
    const int*   dst     = (const int*)d_in[2];
    const float* W_pool1 = (const float*)d_in[3];
    const float* b_pool1 = (const float*)d_in[4];
    const float* W_self1 = (const float*)d_in[5];
    const float* W_neigh1= (const float*)d_in[6];
    const float* bias1   = (const float*)d_in[7];
    const float* W_pool2 = (const float*)d_in[8];
    const float* b_pool2 = (const float*)d_in[9];
    const float* W_self2 = (const float*)d_in[10];
    const float* W_neigh2= (const float*)d_in[11];
    const float* bias2   = (const float*)d_in[12];
    float* out = (float*)d_out;

    __half *dP, *dPl; float* dH;
    cudaGetSymbolAddress((void**)&dP, g_P);
    cudaGetSymbolAddress((void**)&dPl, g_Pl);
    cudaGetSymbolAddress((void**)&dH, g_H);

    // pool v3: 4 nodes per warp
    const int POOL_WARPS = (N_NODES + 3) / 4;
    const int POOLB = (POOL_WARPS * 32 + 255) / 256;

    // K1: flag reset + histogram + layer-1 pool GEMM (tf32)
    hist_gemm_kernel<<<EB4 + NB256, 256>>>((const int4*)dst,
                                           in_feat, W_pool1, b_pool1, dP);
    // K2: single-pass scan
    scan_kernel<<<SCAN_NB, SCAN_BLK>>>();
    // K3: CSR fill
    fill_csr_kernel<<<EB4, 256>>>((const int4*)src, (const int4*)dst);
    // K4: layer-1 pool
    pool_kernel<<<POOLB, 256>>>(dP, dPl);
    // K5: H = leaky(X@Ws1 + Pl@Wn1 + b1)  (tf32, K=128)
    gemm_out_kernel<64, 1, 72><<<NB256, 256>>>(in_feat, dPl, W_self1, W_neigh1,
                                               bias1, dH);
    // K6: P = relu(H@Wp2 + bp2)  (tf32)
    gemm_pool_kernel<<<NB256, 256>>>(dH, W_pool2, b_pool2, dP);
    // K7: layer-2 pool
    pool_kernel<<<POOLB, 256>>>(dP, dPl);
    // K8: out = H@Ws2 + Pl@Wn2 + b2  (tf32, K=128)
    gemm_out_kernel<16, 0, 24><<<NB256, 256>>>(dH, dPl, W_self2, W_neigh2,
                                               bias2, out);
}

// round 12
// speedup vs baseline: 1.5407x; 1.0200x over previous
#include <cuda_runtime.h>
#include <cuda_fp16.h>
#include <cuda_bf16.h>

#define N_NODES 100000
#define N_EDGES 1600000
#define F 64
#define NCLS 16
#define NEG_SLOPE 0.01f

#define SCAN_BLK 1024
#define SCAN_NB ((N_NODES + SCAN_BLK - 1) / SCAN_BLK)   // 98

#define EB4   ((N_EDGES / 4 + 255) / 256)   // 1563 edge blocks
#define NB256 ((N_NODES + 255) / 256)       // 391 node blocks
#define WSTRIDE 72                          // smem W stride for N=64 tiles

typedef unsigned long long ull;

// ---------------- scratch (device globals; zero at module load) --------------
__device__ int    g_deg[N_NODES];
__device__ int    g_off[N_NODES + 1];
__device__ int    g_rank[N_EDGES];       // per-edge rank within its dst segment
__device__ int    g_csr[N_EDGES];
__device__ int    g_scan_incl[SCAN_NB];
__device__ int    g_scan_flag[SCAN_NB];
__device__ __half g_P[(size_t)N_NODES * F];
__device__ __half g_Pl[(size_t)N_NODES * F];
__device__ float  g_H[(size_t)N_NODES * F];

// ---------------- helpers ----------------------------------------------------
__device__ __forceinline__ unsigned hmax2u(unsigned a, unsigned b) {
    __half2 r = __hmax2(*reinterpret_cast<__half2*>(&a),
                        *reinterpret_cast<__half2*>(&b));
    return *reinterpret_cast<unsigned*>(&r);
}
__device__ __forceinline__ unsigned f2tf32(float f) {
    unsigned u; asm("cvt.rna.tf32.f32 %0, %1;" : "=r"(u) : "f"(f)); return u;
}
__device__ __forceinline__ void mma_tf32(float* d, const unsigned* a,
                                         unsigned b0, unsigned b1) {
    asm volatile(
        "mma.sync.aligned.m16n8k8.row.col.f32.tf32.tf32.f32 "
        "{%0,%1,%2,%3}, {%4,%5,%6,%7}, {%8,%9}, {%0,%1,%2,%3};"
        : "+f"(d[0]), "+f"(d[1]), "+f"(d[2]), "+f"(d[3])
        : "r"(a[0]), "r"(a[1]), "r"(a[2]), "r"(a[3]), "r"(b0), "r"(b1));
}

// ---- tf32 pool GEMM body: P[256 rows] = relu(X @ W + b) -> fp16 -------------
__device__ __forceinline__ void gemm_pool_tf32_body(
        const float* __restrict__ X, const unsigned* __restrict__ sWt,
        const float* __restrict__ sbias, __half* __restrict__ Y, int rowbase) {
    int lane = threadIdx.x & 31;
    int warp = threadIdx.x >> 5;
    int g = lane >> 2;
    int t4 = lane & 3;
    int wbase = rowbase + warp * 32;
    const int NMAX = N_NODES - 1;

    int r0a = min(wbase + g,      NMAX), r0b = min(wbase + g + 8,  NMAX);
    int r1a = min(wbase + 16 + g, NMAX), r1b = min(wbase + 24 + g, NMAX);

    float acc[2][8][4];
    #pragma unroll
    for (int T = 0; T < 2; T++)
        #pragma unroll
        for (int nf = 0; nf < 8; nf++) {
            float bb0 = sbias[8 * nf + 2 * t4];
            float bb1 = sbias[8 * nf + 2 * t4 + 1];
            acc[T][nf][0] = bb0; acc[T][nf][1] = bb1;
            acc[T][nf][2] = bb0; acc[T][nf][3] = bb1;
        }

    #pragma unroll
    for (int kf = 0; kf < 8; kf++) {
        int k0 = 8 * kf + t4;
        unsigned a[2][4];
        a[0][0] = f2tf32(__ldg(&X[(size_t)r0a * F + k0]));
        a[0][1] = f2tf32(__ldg(&X[(size_t)r0b * F + k0]));
        a[0][2] = f2tf32(__ldg(&X[(size_t)r0a * F + k0 + 4]));
        a[0][3] = f2tf32(__ldg(&X[(size_t)r0b * F + k0 + 4]));
        a[1][0] = f2tf32(__ldg(&X[(size_t)r1a * F + k0]));
        a[1][1] = f2tf32(__ldg(&X[(size_t)r1b * F + k0]));
        a[1][2] = f2tf32(__ldg(&X[(size_t)r1a * F + k0 + 4]));
        a[1][3] = f2tf32(__ldg(&X[(size_t)r1b * F + k0 + 4]));
        #pragma unroll
        for (int nf = 0; nf < 8; nf++) {
            unsigned b0 = sWt[(8 * kf + t4) * WSTRIDE + 8 * nf + g];
            unsigned b1 = sWt[(8 * kf + t4 + 4) * WSTRIDE + 8 * nf + g];
            mma_tf32(acc[0][nf], a[0], b0, b1);
            mma_tf32(acc[1][nf], a[1], b0, b1);
        }
    }

    #pragma unroll
    for (int T = 0; T < 2; T++) {
        int ra = wbase + 16 * T + g;
        int rb = ra + 8;
        #pragma unroll
        for (int nf = 0; nf < 8; nf++) {
            int col = 8 * nf + 2 * t4;
            if (ra < N_NODES) {
                __half2 h = __floats2half2_rn(fmaxf(acc[T][nf][0], 0.f),
                                              fmaxf(acc[T][nf][1], 0.f));
                *(__half2*)(Y + (size_t)ra * F + col) = h;
            }
            if (rb < N_NODES) {
                __half2 h = __floats2half2_rn(fmaxf(acc[T][nf][2], 0.f),
                                              fmaxf(acc[T][nf][3], 0.f));
                *(__half2*)(Y + (size_t)rb * F + col) = h;
            }
        }
    }
}

__device__ __forceinline__ void stage_w_tf32(
        const float* __restrict__ W, const float* __restrict__ b,
        unsigned* sWt, float* sbias) {
    int t = threadIdx.x;
    for (int i = t; i < F * F; i += 256) {
        int k = i >> 6, n = i & 63;
        sWt[k * WSTRIDE + n] = f2tf32(__ldg(&W[i]));
    }
    if (t < F) sbias[t] = b[t];
}

// ------- K1: merged edge histogram (rank-recording) + layer-1 GEMM -----------
__global__ __launch_bounds__(256) void hist_gemm_kernel(
        const int4* __restrict__ dst4,
        const float* __restrict__ X, const float* __restrict__ W,
        const float* __restrict__ b, __half* __restrict__ Y) {
    __shared__ unsigned sWt[F * WSTRIDE];
    __shared__ float sbias[F];
    int t = threadIdx.x;

    if (blockIdx.x < EB4) {
        if (blockIdx.x == 0 && t < SCAN_NB) g_scan_flag[t] = 0;
        int i = blockIdx.x * 256 + t;
        if (i < N_EDGES / 4) {
            int4 d = __ldg(&dst4[i]);
            int r0 = atomicAdd(&g_deg[d.x], 1);
            int r1 = atomicAdd(&g_deg[d.y], 1);
            int r2 = atomicAdd(&g_deg[d.z], 1);
            int r3 = atomicAdd(&g_deg[d.w], 1);
            int4 rk; rk.x = r0; rk.y = r1; rk.z = r2; rk.w = r3;
            ((int4*)g_rank)[i] = rk;
        }
        return;
    }

    stage_w_tf32(W, b, sWt, sbias);
    __syncthreads();
    gemm_pool_tf32_body(X, sWt, sbias, Y, (blockIdx.x - EB4) * 256);
}

// ---------------- layer-2 pool GEMM (tf32) -----------------------------------
__global__ __launch_bounds__(256) void gemm_pool_kernel(
        const float* __restrict__ X, const float* __restrict__ W,
        const float* __restrict__ b, __half* __restrict__ Y) {
    __shared__ unsigned sWt[F * WSTRIDE];
    __shared__ float sbias[F];
    stage_w_tf32(W, b, sWt, sbias);
    __syncthreads();
    gemm_pool_tf32_body(X, sWt, sbias, Y, blockIdx.x * 256);
}

// ------- single-kernel scan: decoupled lookback ------------------------------
__global__ __launch_bounds__(SCAN_BLK) void scan_kernel() {
    __shared__ int s[SCAN_BLK];
    __shared__ int s_carry;
    int t = threadIdx.x;
    int b = blockIdx.x;
    int idx = b * SCAN_BLK + t;
    int val = 0;
    if (idx < N_NODES) { val = g_deg[idx]; g_deg[idx] = 0; }
    s[t] = val;
    __syncthreads();
    #pragma unroll
    for (int o = 1; o < SCAN_BLK; o <<= 1) {
        int x = (t >= o) ? s[t - o] : 0;
        __syncthreads();
        s[t] += x;
        __syncthreads();
    }
    int incl = s[t];
    if (t == SCAN_BLK - 1) {
        g_scan_incl[b] = incl;
        __threadfence();
        atomicExch(&g_scan_flag[b], 1);
    }
    if (t < 32) {
        int c = 0;
        for (int i = t; i < b; i += 32) {
            while (atomicAdd(&g_scan_flag[i], 0) == 0) { __nanosleep(40); }
            __threadfence();
            c += g_scan_incl[i];
        }
        #pragma unroll
        for (int o = 16; o; o >>= 1) c += __shfl_down_sync(0xffffffff, c, o);
        if (t == 0) s_carry = c;
    }
    __syncthreads();
    int off = s_carry + incl - val;
    if (idx < N_NODES) g_off[idx] = off;
    if (idx == 0) g_off[N_NODES] = N_EDGES;
}

// ------- CSR fill, atomic-free: csr[off[dst] + rank[e]] = src[e] -------------
__global__ void fill_csr_kernel(const int4* __restrict__ src4,
                                const int4* __restrict__ dst4) {
    int i = blockIdx.x * blockDim.x + threadIdx.x;
    if (i < N_EDGES / 4) {
        int4 s = __ldg(&src4[i]);
        int4 d = __ldg(&dst4[i]);
        int4 r = ((const int4*)g_rank)[i];
        g_csr[g_off[d.x] + r.x] = s.x;
        g_csr[g_off[d.y] + r.y] = s.y;
        g_csr[g_off[d.z] + r.z] = s.z;
        g_csr[g_off[d.w] + r.w] = s.w;
    }
}

// ------- segment max pool: 8-lane group per node, 4 nodes/warp, unroll 8 -----
__global__ __launch_bounds__(256) void pool_kernel(const __half* __restrict__ P,
                                                   __half* __restrict__ Pl) {
    int warp_g = (blockIdx.x * 256 + threadIdx.x) >> 5;
    int lane   = threadIdx.x & 31;
    int grp = lane >> 3;
    int sub = lane & 7;
    int node = warp_g * 4 + grp;
    if (node >= N_NODES) return;

    int s0 = g_off[node];
    int s1 = g_off[node + 1];
    unsigned m0 = 0, m1 = 0, m2 = 0, m3 = 0;
    const uint4* Prow = (const uint4*)P;

    if (s0 < s1) {
        int last = s1 - 1;
        for (int e = s0; e < s1; e += 8) {
            int idx[8];
            #pragma unroll
            for (int q = 0; q < 8; q++) idx[q] = g_csr[min(e + q, last)];
            uint4 v[8];
            #pragma unroll
            for (int q = 0; q < 8; q++) v[q] = __ldg(&Prow[idx[q] * 8 + sub]);
            unsigned a0 = hmax2u(hmax2u(v[0].x, v[1].x), hmax2u(v[2].x, v[3].x));
            unsigned b0 = hmax2u(hmax2u(v[4].x, v[5].x), hmax2u(v[6].x, v[7].x));
            unsigned a1 = hmax2u(hmax2u(v[0].y, v[1].y), hmax2u(v[2].y, v[3].y));
            unsigned b1 = hmax2u(hmax2u(v[4].y, v[5].y), hmax2u(v[6].y, v[7].y));
            unsigned a2 = hmax2u(hmax2u(v[0].z, v[1].z), hmax2u(v[2].z, v[3].z));
            unsigned b2 = hmax2u(hmax2u(v[4].z, v[5].z), hmax2u(v[6].z, v[7].z));
            unsigned a3 = hmax2u(hmax2u(v[0].w, v[1].w), hmax2u(v[2].w, v[3].w));
            unsigned b3 = hmax2u(hmax2u(v[4].w, v[5].w), hmax2u(v[6].w, v[7].w));
            m0 = hmax2u(m0, hmax2u(a0, b0));
            m1 = hmax2u(m1, hmax2u(a1, b1));
            m2 = hmax2u(m2, hmax2u(a2, b2));
            m3 = hmax2u(m3, hmax2u(a3, b3));
        }
    }
    uint4 o; o.x = m0; o.y = m1; o.z = m2; o.w = m3;
    ((uint4*)(Pl + (size_t)node * F))[sub] = o;
}

// ------- tf32 out-GEMM: Y[N,DOUT] = act([X | PL] @ [Ws;Wn] + b), K=128 -------
template <int DOUT, int ACT, int SW>
__device__ __forceinline__ void gemm_out_tf32_body(
        const float* __restrict__ X, const __half* __restrict__ PL,
        const unsigned* __restrict__ sWt, const float* __restrict__ sbias,
        float* __restrict__ Y, int rowbase) {
    const int NF = DOUT / 8;
    int lane = threadIdx.x & 31;
    int warp = threadIdx.x >> 5;
    int g = lane >> 2;
    int t4 = lane & 3;
    int wbase = rowbase + warp * 32;
    const int NMAX = N_NODES - 1;

    int r0a = min(wbase + g,      NMAX), r0b = min(wbase + g + 8,  NMAX);
    int r1a = min(wbase + 16 + g, NMAX), r1b = min(wbase + 24 + g, NMAX);

    float acc[2][NF][4];
    #pragma unroll
    for (int T = 0; T < 2; T++)
        #pragma unroll
        for (int nf = 0; nf < NF; nf++) {
            float bb0 = sbias[8 * nf + 2 * t4];
            float bb1 = sbias[8 * nf + 2 * t4 + 1];
            acc[T][nf][0] = bb0; acc[T][nf][1] = bb1;
            acc[T][nf][2] = bb0; acc[T][nf][3] = bb1;
        }

    #pragma unroll
    for (int kf = 0; kf < 8; kf++) {
        int k0 = 8 * kf + t4;
        unsigned a[2][4];
        a[0][0] = f2tf32(__ldg(&X[(size_t)r0a * F + k0]));
        a[0][1] = f2tf32(__ldg(&X[(size_t)r0b * F + k0]));
        a[0][2] = f2tf32(__ldg(&X[(size_t)r0a * F + k0 + 4]));
        a[0][3] = f2tf32(__ldg(&X[(size_t)r0b * F + k0 + 4]));
        a[1][0] = f2tf32(__ldg(&X[(size_t)r1a * F + k0]));
        a[1][1] = f2tf32(__ldg(&X[(size_t)r1b * F + k0]));
        a[1][2] = f2tf32(__ldg(&X[(size_t)r1a * F + k0 + 4]));
        a[1][3] = f2tf32(__ldg(&X[(size_t)r1b * F + k0 + 4]));
        #pragma unroll
        for (int nf = 0; nf < NF; nf++) {
            unsigned b0 = sWt[(8 * kf + t4) * SW + 8 * nf + g];
            unsigned b1 = sWt[(8 * kf + t4 + 4) * SW + 8 * nf + g];
            mma_tf32(acc[0][nf], a[0], b0, b1);
            mma_tf32(acc[1][nf], a[1], b0, b1);
        }
    }
    #pragma unroll
    for (int kf = 0; kf < 8; kf++) {
        int k0 = 8 * kf + t4;
        unsigned a[2][4];
        a[0][0] = f2tf32(__half2float(__ldg(&PL[(size_t)r0a * F + k0])));
        a[0][1] = f2tf32(__half2float(__ldg(&PL[(size_t)r0b * F + k0])));
        a[0][2] = f2tf32(__half2float(__ldg(&PL[(size_t)r0a * F + k0 + 4])));
        a[0][3] = f2tf32(__half2float(__ldg(&PL[(size_t)r0b * F + k0 + 4])));
        a[1][0] = f2tf32(__half2float(__ldg(&PL[(size_t)r1a * F + k0])));
        a[1][1] = f2tf32(__half2float(__ldg(&PL[(size_t)r1b * F + k0])));
        a[1][2] = f2tf32(__half2float(__ldg(&PL[(size_t)r1a * F + k0 + 4])));
        a[1][3] = f2tf32(__half2float(__ldg(&PL[(size_t)r1b * F + k0 + 4])));
        #pragma unroll
        for (int nf = 0; nf < NF; nf++) {
            unsigned b0 = sWt[(64 + 8 * kf + t4) * SW + 8 * nf + g];
            unsigned b1 = sWt[(64 + 8 * kf + t4 + 4) * SW + 8 * nf + g];
            mma_tf32(acc[0][nf], a[0], b0, b1);
            mma_tf32(acc[1][nf], a[1], b0, b1);
        }
    }

    #pragma unroll
    for (int T = 0; T < 2; T++) {
        int ra = wbase + 16 * T + g;
        int rb = ra + 8;
        #pragma unroll
        for (int nf = 0; nf < NF; nf++) {
            int col = 8 * nf + 2 * t4;
            float v0 = acc[T][nf][0], v1 = acc[T][nf][1];
            float v2 = acc[T][nf][2], v3 = acc[T][nf][3];
            if (ACT == 1) {
                v0 = (v0 >= 0.f) ? v0 : NEG_SLOPE * v0;
                v1 = (v1 >= 0.f) ? v1 : NEG_SLOPE * v1;
                v2 = (v2 >= 0.f) ? v2 : NEG_SLOPE * v2;
                v3 = (v3 >= 0.f) ? v3 : NEG_SLOPE * v3;
            }
            if (ra < N_NODES) {
                float2 o; o.x = v0; o.y = v1;
                *(float2*)(Y + (size_t)ra * DOUT + col) = o;
            }
            if (rb < N_NODES) {
                float2 o; o.x = v2; o.y = v3;
                *(float2*)(Y + (size_t)rb * DOUT + col) = o;
            }
        }
    }
}

template <int DOUT, int SW>
__device__ __forceinline__ void stage_w2_tf32(
        const float* __restrict__ Ws, const float* __restrict__ Wn,
        const float* __restrict__ b, unsigned* sWt, float* sbias) {
    int t = threadIdx.x;
    for (int i = t; i < F * DOUT; i += 256) {
        int k = i / DOUT, n = i % DOUT;
        sWt[k * SW + n]        = f2tf32(__ldg(&Ws[i]));
        sWt[(64 + k) * SW + n] = f2tf32(__ldg(&Wn[i]));
    }
    if (t < DOUT) sbias[t] = b[t];
}

template <int DOUT, int ACT, int SW>
__global__ __launch_bounds__(256) void gemm_out_kernel(
        const float* __restrict__ X, const __half* __restrict__ PL,
        const float* __restrict__ Ws, const float* __restrict__ Wn,
        const float* __restrict__ b, float* __restrict__ Y) {
    __shared__ unsigned sWt[128 * SW];
    __shared__ float sbias[DOUT];
    stage_w2_tf32<DOUT, SW>(Ws, Wn, b, sWt, sbias);
    __syncthreads();
    gemm_out_tf32_body<DOUT, ACT, SW>(X, PL, sWt, sbias, Y, blockIdx.x * 256);
}

// ---------------- launch -----------------------------------------------------
extern "C" void kernel_launch(void* const* d_in, const int* in_sizes, int n_in,
                              void* d_out, int out_size) {
    const float* in_feat = (const float*)d_in[0];
    const int*   src     = (const int*)d_in[1];
    const int*   dst     = (const int*)d_in[2];
    const float* W_pool1 = (const float*)d_in[3];
    const float* b_pool1 = (const float*)d_in[4];
    const float* W_self1 = (const float*)d_in[5];
    const float* W_neigh1= (const float*)d_in[6];
    const float* bias1   = (const float*)d_in[7];
    const float* W_pool2 = (const float*)d_in[8];
    const float* b_pool2 = (const float*)d_in[9];
    const float* W_self2 = (const float*)d_in[10];
    const float* W_neigh2= (const float*)d_in[11];
    const float* bias2   = (const float*)d_in[12];
    float* out = (float*)d_out;

    __half *dP, *dPl; float* dH;
    cudaGetSymbolAddress((void**)&dP, g_P);
    cudaGetSymbolAddress((void**)&dPl, g_Pl);
    cudaGetSymbolAddress((void**)&dH, g_H);

    const int POOL_WARPS = (N_NODES + 3) / 4;
    const int POOLB = (POOL_WARPS * 32 + 255) / 256;

    // K1: flag reset + rank-recording histogram + layer-1 pool GEMM (tf32)
    hist_gemm_kernel<<<EB4 + NB256, 256>>>((const int4*)dst,
                                           in_feat, W_pool1, b_pool1, dP);
    // K2: single-pass scan (offsets only; no cursors)
    scan_kernel<<<SCAN_NB, SCAN_BLK>>>();
    // K3: atomic-free CSR fill
    fill_csr_kernel<<<EB4, 256>>>((const int4*)src, (const int4*)dst);
    // K4: layer-1 pool
    pool_kernel<<<POOLB, 256>>>(dP, dPl);
    // K5: H = leaky(X@Ws1 + Pl@Wn1 + b1)  (tf32, K=128)
    gemm_out_kernel<64, 1, 72><<<NB256, 256>>>(in_feat, dPl, W_self1, W_neigh1,
                                               bias1, dH);
    // K6: P = relu(H@Wp2 + bp2)  (tf32)
    gemm_pool_kernel<<<NB256, 256>>>(dH, W_pool2, b_pool2, dP);
    // K7: layer-2 pool
    pool_kernel<<<POOLB, 256>>>(dP, dPl);
    // K8: out = H@Ws2 + Pl@Wn2 + b2  (tf32, K=128)
    gemm_out_kernel<16, 0, 24><<<NB256, 256>>>(dH, dPl, W_self2, W_neigh2,
                                               bias2, out);
}